// round 10
// baseline (speedup 1.0000x reference)
#include <cuda_runtime.h>
#include <cuda_bf16.h>
#include <math.h>
#include <stdint.h>

#define NB 2
#define NS 2048
#define ND 1024
#define NH 16
#define HDIM 64
#define MROWS (NB*NS)
#define RWORDS (ND/2)          // 512 u32 words per 1024-elem bf16 row

// ---- static scratch (no allocations allowed) ----
__device__ uint32_t g_inqh[MROWS*RWORDS], g_inql[MROWS*RWORDS];
__device__ uint32_t g_inkh[MROWS*RWORDS], g_inkl[MROWS*RWORDS];
__device__ uint32_t g_invh[MROWS*RWORDS], g_invl[MROWS*RWORDS];
__device__ uint32_t g_wh[4*ND*RWORDS], g_wl[4*ND*RWORDS];
__device__ uint32_t g_qh[NB*NH*NS*HDIM/2], g_ql[NB*NH*NS*HDIM/2];
__device__ uint32_t g_kh[NB*NH*NS*HDIM/2], g_kl[NB*NH*NS*HDIM/2];
__device__ uint32_t g_vh[NB*NH*NS*HDIM/2], g_vl[NB*NH*NS*HDIM/2];
__device__ uint32_t g_ch[MROWS*RWORDS], g_cl[MROWS*RWORDS];

#define QSCALE 0.18033688011f      // 0.125 * log2(e)

#define MMA16816(c, a, b) \
  asm volatile("mma.sync.aligned.m16n8k16.row.col.f32.bf16.bf16.f32 " \
    "{%0,%1,%2,%3}, {%4,%5,%6,%7}, {%8,%9}, {%0,%1,%2,%3};" \
    : "+f"((c)[0]), "+f"((c)[1]), "+f"((c)[2]), "+f"((c)[3]) \
    : "r"((a)[0]), "r"((a)[1]), "r"((a)[2]), "r"((a)[3]), \
      "r"((b)[0]), "r"((b)[1]))

__device__ __forceinline__ void cvt_pair(float x, float y, uint32_t& hi, uint32_t& lo) {
    __nv_bfloat162 h = __floats2bfloat162_rn(x, y);
    float hx = __bfloat162float(__low2bfloat16(h));
    float hy = __bfloat162float(__high2bfloat16(h));
    __nv_bfloat162 l = __floats2bfloat162_rn(x - hx, y - hy);
    hi = *reinterpret_cast<uint32_t*>(&h);
    lo = *reinterpret_cast<uint32_t*>(&l);
}
__device__ __forceinline__ float ex2f(float x) {
    float y; asm("ex2.approx.ftz.f32 %0, %1;" : "=f"(y) : "f"(x)); return y;
}
__device__ __forceinline__ uint32_t smem_u32(const void* p) {
    uint32_t a;
    asm("{ .reg .u64 t; cvta.to.shared.u64 t, %1; cvt.u32.u64 %0, t; }" : "=r"(a) : "l"(p));
    return a;
}
__device__ __forceinline__ void ldsm_x4(uint32_t& r0, uint32_t& r1, uint32_t& r2, uint32_t& r3,
                                        uint32_t a) {
    asm volatile("ldmatrix.sync.aligned.m8n8.x4.shared.b16 {%0,%1,%2,%3}, [%4];"
                 : "=r"(r0), "=r"(r1), "=r"(r2), "=r"(r3) : "r"(a));
}
__device__ __forceinline__ void ldsm_x4_t(uint32_t& r0, uint32_t& r1, uint32_t& r2, uint32_t& r3,
                                          uint32_t a) {
    asm volatile("ldmatrix.sync.aligned.m8n8.x4.trans.shared.b16 {%0,%1,%2,%3}, [%4];"
                 : "=r"(r0), "=r"(r1), "=r"(r2), "=r"(r3) : "r"(a));
}
__device__ __forceinline__ void cp16(uint32_t dst, const void* src) {
    asm volatile("cp.async.cg.shared.global [%0], [%1], 16;" :: "r"(dst), "l"(src) : "memory");
}
__device__ __forceinline__ void cp_commit() {
    asm volatile("cp.async.commit_group;" ::: "memory");
}
template<int N> __device__ __forceinline__ void cp_wait() {
    asm volatile("cp.async.wait_group %0;" :: "n"(N) : "memory");
}

// ---------------------------------------------------------------------------
// fp32 -> bf16 hi/lo plane converter
// ---------------------------------------------------------------------------
__global__ __launch_bounds__(256) void cvt_planes(
    const float* s0, uint32_t* h0, uint32_t* l0,
    const float* s1, uint32_t* h1, uint32_t* l1,
    const float* s2, uint32_t* h2, uint32_t* l2,
    const float* s3, uint32_t* h3, uint32_t* l3)
{
    const float* s; uint32_t *ph, *pl;
    switch (blockIdx.z) {
        case 0: s = s0; ph = h0; pl = l0; break;
        case 1: s = s1; ph = h1; pl = l1; break;
        case 2: s = s2; ph = h2; pl = l2; break;
        default: s = s3; ph = h3; pl = l3; break;
    }
    int i = blockIdx.x * 256 + threadIdx.x;
    float4 a = ((const float4*)s)[2 * i];
    float4 b = ((const float4*)s)[2 * i + 1];
    uint32_t h[4], l[4];
    cvt_pair(a.x, a.y, h[0], l[0]);
    cvt_pair(a.z, a.w, h[1], l[1]);
    cvt_pair(b.x, b.y, h[2], l[2]);
    cvt_pair(b.z, b.w, h[3], l[3]);
    ((uint4*)ph)[i] = make_uint4(h[0], h[1], h[2], h[3]);
    ((uint4*)pl)[i] = make_uint4(l[0], l[1], l[2], l[3]);
}

// ---------------------------------------------------------------------------
// Plane GEMM (unchanged from R9: cp.async 2-stage, 2 CTAs/SM)
// ---------------------------------------------------------------------------
struct GP {
    const uint32_t *Ah, *Al, *Bh, *Bl;
    const float* bias;
    float* C; uint32_t *Ph, *Pl; float scale;
};
#define GSTAGE_B 40960

__global__ __launch_bounds__(256, 2) void gemm_planes(GP a0, GP a1, GP a2, int headmode)
{
    GP g = (blockIdx.z == 0) ? a0 : (blockIdx.z == 1) ? a1 : a2;
    extern __shared__ uint32_t smg[];
    const uint32_t sb = smem_u32(smg);

    const int tid = threadIdx.x;
    const int warp = tid >> 5;
    const int lane = tid & 31;
    const int r4 = lane >> 2, q4 = lane & 3;
    const int m0w = (warp >> 2) * 64;
    const int n0w = (warp & 3) * 32;
    const int mBase = blockIdx.y * 128;
    const int nBase = blockIdx.x * 128;

    const uint32_t* srcA[4] = {
        g.Ah + (size_t)mBase * RWORDS, g.Al + (size_t)mBase * RWORDS,
        g.Bh + (size_t)nBase * RWORDS, g.Bl + (size_t)nBase * RWORDS };

    const uint32_t aOffH = (uint32_t)((m0w + (lane & 15)) * 80 + (lane >> 4) * 16);
    const uint32_t aOffL = aOffH + 10240u;
    const int bsel = lane >> 3;
    const uint32_t bOff = (uint32_t)((bsel < 2 ? 20480 : 30720) +
                                     (n0w + (lane & 7)) * 80 + (bsel & 1) * 16);

    float acc[4][4][4];
#pragma unroll
    for (int mf = 0; mf < 4; mf++)
#pragma unroll
        for (int nf = 0; nf < 4; nf++)
#pragma unroll
            for (int c = 0; c < 4; c++) acc[mf][nf][c] = 0.f;

    auto issue = [&](int stage, int ch) {
#pragma unroll
        for (int it = 0; it < 8; it++) {
            int gi = tid + it * 256;
            int pl = gi >> 9, gg = gi & 511;
            int row = gg >> 2, seg = gg & 3;
            const uint32_t* src = srcA[pl] + (size_t)row * RWORDS + ch * 16 + seg * 4;
            uint32_t dst = sb + stage * GSTAGE_B + pl * 10240 + row * 80 + seg * 16;
            cp16(dst, src);
        }
        cp_commit();
    };

    issue(0, 0);
    issue(1, 1);

    for (int ch = 0; ch < 32; ch++) {
        if (ch < 31) cp_wait<1>(); else cp_wait<0>();
        __syncthreads();
        const uint32_t sBase = sb + (ch & 1) * GSTAGE_B;

#pragma unroll
        for (int ks = 0; ks < 2; ks++) {
            const uint32_t ko = ks * 32;
            uint32_t bh[4][2], bl[4][2];
#pragma unroll
            for (int nf = 0; nf < 4; nf++)
                ldsm_x4(bh[nf][0], bh[nf][1], bl[nf][0], bl[nf][1],
                        sBase + bOff + nf * 640 + ko);
#pragma unroll
            for (int mf = 0; mf < 4; mf++) {
                uint32_t ah[4], al[4];
                ldsm_x4(ah[0], ah[1], ah[2], ah[3], sBase + aOffH + mf * 1280 + ko);
                ldsm_x4(al[0], al[1], al[2], al[3], sBase + aOffL + mf * 1280 + ko);
#pragma unroll
                for (int nf = 0; nf < 4; nf++) {
                    MMA16816(acc[mf][nf], ah, bh[nf]);
                    MMA16816(acc[mf][nf], ah, bl[nf]);
                    MMA16816(acc[mf][nf], al, bh[nf]);
                }
            }
        }
        __syncthreads();
        if (ch + 2 < 32) issue(ch & 1, ch + 2);
    }

#pragma unroll
    for (int nf = 0; nf < 4; nf++) {
        const int n = nBase + n0w + nf * 8 + q4 * 2;
        const float b0 = __ldg(g.bias + n);
        const float b1 = __ldg(g.bias + n + 1);
#pragma unroll
        for (int mf = 0; mf < 4; mf++) {
#pragma unroll
            for (int half = 0; half < 2; half++) {
                const int m = mBase + m0w + mf * 16 + r4 + half * 8;
                float v0 = (acc[mf][nf][half * 2] + b0) * g.scale;
                float v1 = (acc[mf][nf][half * 2 + 1] + b1) * g.scale;
                if (headmode) {
                    uint32_t hi, lo;
                    cvt_pair(v0, v1, hi, lo);
                    int b = m >> 11, s = m & (NS - 1);
                    int hh = n >> 6, e = n & 63;
                    size_t wo = (((size_t)((b * NH + hh) * NS + s)) * HDIM + e) >> 1;
                    g.Ph[wo] = hi;
                    g.Pl[wo] = lo;
                } else {
                    *(float2*)(g.C + (size_t)m * ND + n) = make_float2(v0, v1);
                }
            }
        }
    }
}

// ---------------------------------------------------------------------------
// Tensor-core flash attention: BQ=64, 128 threads, target 3 CTAs/SM.
// Split-3 QK^T and PV. Mask folded into S accumulator init (additive -9e9,
// bit-identical to overwrite since masked cols underflow exp2 to 0).
// stage layout (bytes): Kh[0] Kl[9216] Vh[18432] Vl[27648]; 2 stages; maskF after.
// ---------------------------------------------------------------------------
#define KSTR 36                // u32 words per row (144B)
#define ASTAGE_B 36864         // 4 planes x 64 rows x 144B

__global__ __launch_bounds__(128, 3) void attn_mma(const uint32_t* __restrict__ qh,
                                                   const uint32_t* __restrict__ ql,
                                                   const uint32_t* __restrict__ kh,
                                                   const uint32_t* __restrict__ kl,
                                                   const uint32_t* __restrict__ vh,
                                                   const uint32_t* __restrict__ vl,
                                                   const int* __restrict__ mask,
                                                   uint32_t* __restrict__ ch_out,
                                                   uint32_t* __restrict__ cl_out)
{
    extern __shared__ uint32_t dynsm[];
    const uint32_t sb = smem_u32(dynsm);
    float* sMkF = (float*)(dynsm + 2 * (ASTAGE_B / 4));   // 64 float addends
    uint32_t* sQh = dynsm;                 // phase 1 only (64*36 words each)
    uint32_t* sQl = dynsm + 64 * KSTR;

    const int tid = threadIdx.x;
    const int warp = tid >> 5;
    const int lane = tid & 31;
    const int r4 = lane >> 2, q4 = lane & 3;
    const int qt = blockIdx.x;     // 0..31 (64-row q tiles)
    const int bh = blockIdx.y;     // 0..31
    const int b = bh >> 4, h = bh & 15;
    const size_t headW = (size_t)bh * NS * (HDIM / 2);

    // ---- Phase 1: stage Q planes (64 rows), load persistent A-frags ----
    {
        const uint32_t* pQh = qh + headW + (size_t)qt * 64 * 32;
        const uint32_t* pQl = ql + headW + (size_t)qt * 64 * 32;
#pragma unroll
        for (int it = 0; it < 8; it++) {
            int gi = tid + it * 128;       // 0..1023
            int pl = gi >> 9, gg = gi & 511;
            int row = gg >> 3, w4 = (gg & 7) * 4;
            uint4 v = *(const uint4*)((pl ? pQl : pQh) + row * 32 + w4);
            *(uint4*)((pl ? sQl : sQh) + row * KSTR + w4) = v;
        }
    }
    __syncthreads();
    uint32_t Qh[4][4], Ql[4][4];
#pragma unroll
    for (int kf = 0; kf < 4; kf++) {
        int off = (16 * warp + r4) * KSTR + 8 * kf + q4;
        Qh[kf][0] = sQh[off];              Qh[kf][1] = sQh[off + 8 * KSTR];
        Qh[kf][2] = sQh[off + 4];          Qh[kf][3] = sQh[off + 8 * KSTR + 4];
        Ql[kf][0] = sQl[off];              Ql[kf][1] = sQl[off + 8 * KSTR];
        Ql[kf][2] = sQl[off + 4];          Ql[kf][3] = sQl[off + 8 * KSTR + 4];
    }
    __syncthreads();   // stage area reusable

    const uint32_t* srcP[4] = {kh + headW, kl + headW, vh + headW, vl + headW};
    auto issue = [&](int stage, int kt) {
#pragma unroll
        for (int it = 0; it < 16; it++) {
            int gi = tid + it * 128;       // 0..2047
            int pl = gi >> 9, gg = gi & 511;
            int row = gg >> 3, seg = gg & 7;
            const uint32_t* src = srcP[pl] + (size_t)kt * 2048 + row * 32 + seg * 4;
            uint32_t dst = sb + stage * ASTAGE_B + pl * 9216 + row * 144 + seg * 16;
            cp16(dst, src);
        }
        cp_commit();
    };

    const int ksel = lane >> 3;
    const uint32_t kOff = (uint32_t)((ksel < 2 ? 0 : 9216) +
                                     (lane & 7) * 144 + (ksel & 1) * 16);
    const uint32_t vOff = (uint32_t)((lane < 16 ? 18432 : 27648) + (lane & 15) * 144);

    float O[8][4];
    float mI0 = -INFINITY, mI1 = -INFINITY, lI0 = 0.f, lI1 = 0.f;
#pragma unroll
    for (int nf = 0; nf < 8; nf++)
#pragma unroll
        for (int c = 0; c < 4; c++) O[nf][c] = 0.f;

    const int* mrow = mask + (size_t)b * NS;
    float mkldF = (tid < 64 && mrow[tid]) ? -9e9f : 0.f;

    issue(0, 0);
    issue(1, 1);

    for (int kt = 0; kt < 32; kt++) {
        if (tid < 64) sMkF[tid] = mkldF;      // safe: prev iter ended with sync
        if (kt < 31) cp_wait<1>(); else cp_wait<0>();
        __syncthreads();
        const uint32_t sStage = sb + (kt & 1) * ASTAGE_B;

        // ---- S = mask_addend + Q K^T (split-3) ----
        float S[8][4];
#pragma unroll
        for (int nf = 0; nf < 8; nf++) {
            float2 ma = *(const float2*)(sMkF + 8 * nf + 2 * q4);
            S[nf][0] = ma.x; S[nf][1] = ma.y;
            S[nf][2] = ma.x; S[nf][3] = ma.y;
        }
#pragma unroll
        for (int kf = 0; kf < 4; kf++) {
#pragma unroll
            for (int nf = 0; nf < 8; nf++) {
                uint32_t kh2[2], kl2[2];
                ldsm_x4(kh2[0], kh2[1], kl2[0], kl2[1],
                        sStage + kOff + (uint32_t)(nf * 1152 + kf * 32));
                MMA16816(S[nf], Qh[kf], kh2);
                MMA16816(S[nf], Qh[kf], kl2);
                MMA16816(S[nf], Ql[kf], kh2);
            }
        }

        // ---- online softmax (exp2 domain) ----
        float mt0 = -INFINITY, mt1 = -INFINITY;
#pragma unroll
        for (int nf = 0; nf < 8; nf++) {
            mt0 = fmaxf(mt0, fmaxf(S[nf][0], S[nf][1]));
            mt1 = fmaxf(mt1, fmaxf(S[nf][2], S[nf][3]));
        }
        mt0 = fmaxf(mt0, __shfl_xor_sync(0xffffffffu, mt0, 1));
        mt0 = fmaxf(mt0, __shfl_xor_sync(0xffffffffu, mt0, 2));
        mt1 = fmaxf(mt1, __shfl_xor_sync(0xffffffffu, mt1, 1));
        mt1 = fmaxf(mt1, __shfl_xor_sync(0xffffffffu, mt1, 2));

        float mN0 = fmaxf(mI0, mt0), mN1 = fmaxf(mI1, mt1);
        float f0 = ex2f(mI0 - mN0), f1 = ex2f(mI1 - mN1);
        float rs0 = 0.f, rs1 = 0.f;
#pragma unroll
        for (int nf = 0; nf < 8; nf++) {
            S[nf][0] = ex2f(S[nf][0] - mN0);
            S[nf][1] = ex2f(S[nf][1] - mN0);
            S[nf][2] = ex2f(S[nf][2] - mN1);
            S[nf][3] = ex2f(S[nf][3] - mN1);
            rs0 += S[nf][0] + S[nf][1];
            rs1 += S[nf][2] + S[nf][3];
        }
        rs0 += __shfl_xor_sync(0xffffffffu, rs0, 1);
        rs0 += __shfl_xor_sync(0xffffffffu, rs0, 2);
        rs1 += __shfl_xor_sync(0xffffffffu, rs1, 1);
        rs1 += __shfl_xor_sync(0xffffffffu, rs1, 2);
        lI0 = lI0 * f0 + rs0;
        lI1 = lI1 * f1 + rs1;
        mI0 = mN0; mI1 = mN1;
#pragma unroll
        for (int nf = 0; nf < 8; nf++) {
            O[nf][0] *= f0; O[nf][1] *= f0;
            O[nf][2] *= f1; O[nf][3] *= f1;
        }

        // ---- O += P V (split-3; per-kf P conversion to cap registers) ----
#pragma unroll
        for (int kf = 0; kf < 4; kf++) {
            uint32_t ph[4], pl2[4];
            cvt_pair(S[2*kf][0],     S[2*kf][1],     ph[0], pl2[0]);
            cvt_pair(S[2*kf][2],     S[2*kf][3],     ph[1], pl2[1]);
            cvt_pair(S[2*kf + 1][0], S[2*kf + 1][1], ph[2], pl2[2]);
            cvt_pair(S[2*kf + 1][2], S[2*kf + 1][3], ph[3], pl2[3]);
            uint32_t abase = sStage + vOff + (uint32_t)(kf * 2304);
#pragma unroll
            for (int nf = 0; nf < 8; nf++) {
                uint32_t vh2[2], vl2[2];
                ldsm_x4_t(vh2[0], vh2[1], vl2[0], vl2[1], abase + nf * 16);
                MMA16816(O[nf], ph, vh2);
                MMA16816(O[nf], ph, vl2);
                MMA16816(O[nf], pl2, vh2);
            }
        }

        __syncthreads();
        if (kt + 2 < 32) issue(kt & 1, kt + 2);
        if (kt + 1 < 32 && tid < 64)
            mkldF = mrow[(kt + 1) * 64 + tid] ? -9e9f : 0.f;
    }

    // ---- normalize + write ctx planes [b][s][h*64+e] ----
    const float inv0 = 1.f / lI0;
    const float inv1 = 1.f / lI1;
    const int row0 = qt * 64 + 16 * warp + r4;
#pragma unroll
    for (int nf = 0; nf < 8; nf++) {
        uint32_t hi, lo;
        size_t wo0 = (((size_t)(b * NS + row0)) * ND + h * HDIM + 8 * nf + 2 * q4) >> 1;
        size_t wo1 = (((size_t)(b * NS + row0 + 8)) * ND + h * HDIM + 8 * nf + 2 * q4) >> 1;
        cvt_pair(O[nf][0] * inv0, O[nf][1] * inv0, hi, lo);
        ch_out[wo0] = hi; cl_out[wo0] = lo;
        cvt_pair(O[nf][2] * inv1, O[nf][3] * inv1, hi, lo);
        ch_out[wo1] = hi; cl_out[wo1] = lo;
    }
}

extern "C" void kernel_launch(void* const* d_in, const int* in_sizes, int n_in,
                              void* d_out, int out_size)
{
    const float* q  = (const float*)d_in[0];
    const float* k  = (const float*)d_in[1];
    const float* v  = (const float*)d_in[2];
    const int* mask = (const int*)d_in[3];
    const float* Wq = (const float*)d_in[4];
    const float* bq = (const float*)d_in[5];
    const float* Wk = (const float*)d_in[6];
    const float* bk = (const float*)d_in[7];
    const float* Wv = (const float*)d_in[8];
    const float* bv = (const float*)d_in[9];
    const float* Wo = (const float*)d_in[10];
    const float* bo = (const float*)d_in[11];
    float* out = (float*)d_out;

    uint32_t *inqh, *inql, *inkh, *inkl, *invh, *invl, *wh, *wl;
    uint32_t *qh_d, *ql_d, *kh_d, *kl_d, *vh_d, *vl_d, *ch_d, *cl_d;
    cudaGetSymbolAddress((void**)&inqh, g_inqh); cudaGetSymbolAddress((void**)&inql, g_inql);
    cudaGetSymbolAddress((void**)&inkh, g_inkh); cudaGetSymbolAddress((void**)&inkl, g_inkl);
    cudaGetSymbolAddress((void**)&invh, g_invh); cudaGetSymbolAddress((void**)&invl, g_invl);
    cudaGetSymbolAddress((void**)&wh, g_wh);     cudaGetSymbolAddress((void**)&wl, g_wl);
    cudaGetSymbolAddress((void**)&qh_d, g_qh);   cudaGetSymbolAddress((void**)&ql_d, g_ql);
    cudaGetSymbolAddress((void**)&kh_d, g_kh);   cudaGetSymbolAddress((void**)&kl_d, g_kl);
    cudaGetSymbolAddress((void**)&vh_d, g_vh);   cudaGetSymbolAddress((void**)&vl_d, g_vl);
    cudaGetSymbolAddress((void**)&ch_d, g_ch);   cudaGetSymbolAddress((void**)&cl_d, g_cl);

    const int WSTRIDE = ND * RWORDS;

    cvt_planes<<<dim3(MROWS * ND / 8 / 256, 1, 3), 256>>>(
        q, inqh, inql, k, inkh, inkl, v, invh, invl, q, inqh, inql);
    cvt_planes<<<dim3(ND * ND / 8 / 256, 1, 4), 256>>>(
        Wq, wh, wl, Wk, wh + WSTRIDE, wl + WSTRIDE,
        Wv, wh + 2 * WSTRIDE, wl + 2 * WSTRIDE, Wo, wh + 3 * WSTRIDE, wl + 3 * WSTRIDE);

    const int smem_gemm = 2 * GSTAGE_B;                 // 81920
    cudaFuncSetAttribute(gemm_planes, cudaFuncAttributeMaxDynamicSharedMemorySize, smem_gemm);
    const int smem_attn = 2 * ASTAGE_B + 64 * 4;        // 73984
    cudaFuncSetAttribute(attn_mma, cudaFuncAttributeMaxDynamicSharedMemorySize, smem_attn);

    GP aq{inqh, inql, wh, wl, bq, nullptr, qh_d, ql_d, QSCALE};
    GP ak{inkh, inkl, wh + WSTRIDE, wl + WSTRIDE, bk, nullptr, kh_d, kl_d, 1.f};
    GP av{invh, invl, wh + 2 * WSTRIDE, wl + 2 * WSTRIDE, bv, nullptr, vh_d, vl_d, 1.f};
    gemm_planes<<<dim3(ND / 128, MROWS / 128, 3), 256, smem_gemm>>>(aq, ak, av, 1);

    attn_mma<<<dim3(NS / 64, NB * NH), 128, smem_attn>>>(qh_d, ql_d, kh_d, kl_d,
                                                         vh_d, vl_d, mask, ch_d, cl_d);

    GP ao{ch_d, cl_d, wh + 3 * WSTRIDE, wl + 3 * WSTRIDE, bo, out, nullptr, nullptr, 1.f};
    gemm_planes<<<dim3(ND / 128, MROWS / 128, 1), 256, smem_gemm>>>(ao, ao, ao, 0);
}

// round 11
// speedup vs baseline: 1.0744x; 1.0744x over previous
#include <cuda_runtime.h>
#include <cuda_bf16.h>
#include <math.h>
#include <stdint.h>

#define NB 2
#define NS 2048
#define ND 1024
#define NH 16
#define HDIM 64
#define MROWS (NB*NS)
#define RWORDS (ND/2)          // 512 u32 words per 1024-elem bf16 row

// ---- static scratch (no allocations allowed) ----
__device__ uint32_t g_inqh[MROWS*RWORDS], g_inql[MROWS*RWORDS];
__device__ uint32_t g_inkh[MROWS*RWORDS], g_inkl[MROWS*RWORDS];
__device__ uint32_t g_invh[MROWS*RWORDS], g_invl[MROWS*RWORDS];
__device__ uint32_t g_wh[4*ND*RWORDS], g_wl[4*ND*RWORDS];
__device__ uint32_t g_qh[NB*NH*NS*HDIM/2], g_ql[NB*NH*NS*HDIM/2];
__device__ uint32_t g_kh[NB*NH*NS*HDIM/2], g_kl[NB*NH*NS*HDIM/2];
__device__ uint32_t g_vh[NB*NH*NS*HDIM/2], g_vl[NB*NH*NS*HDIM/2];
__device__ uint32_t g_ch[MROWS*RWORDS], g_cl[MROWS*RWORDS];

#define QSCALE 0.18033688011f      // 0.125 * log2(e)

#define MMA16816(c, a, b) \
  asm volatile("mma.sync.aligned.m16n8k16.row.col.f32.bf16.bf16.f32 " \
    "{%0,%1,%2,%3}, {%4,%5,%6,%7}, {%8,%9}, {%0,%1,%2,%3};" \
    : "+f"((c)[0]), "+f"((c)[1]), "+f"((c)[2]), "+f"((c)[3]) \
    : "r"((a)[0]), "r"((a)[1]), "r"((a)[2]), "r"((a)[3]), \
      "r"((b)[0]), "r"((b)[1]))

__device__ __forceinline__ void cvt_pair(float x, float y, uint32_t& hi, uint32_t& lo) {
    __nv_bfloat162 h = __floats2bfloat162_rn(x, y);
    float hx = __bfloat162float(__low2bfloat16(h));
    float hy = __bfloat162float(__high2bfloat16(h));
    __nv_bfloat162 l = __floats2bfloat162_rn(x - hx, y - hy);
    hi = *reinterpret_cast<uint32_t*>(&h);
    lo = *reinterpret_cast<uint32_t*>(&l);
}
__device__ __forceinline__ float ex2f(float x) {
    float y; asm("ex2.approx.ftz.f32 %0, %1;" : "=f"(y) : "f"(x)); return y;
}
__device__ __forceinline__ uint32_t smem_u32(const void* p) {
    uint32_t a;
    asm("{ .reg .u64 t; cvta.to.shared.u64 t, %1; cvt.u32.u64 %0, t; }" : "=r"(a) : "l"(p));
    return a;
}
__device__ __forceinline__ void ldsm_x4(uint32_t& r0, uint32_t& r1, uint32_t& r2, uint32_t& r3,
                                        uint32_t a) {
    asm volatile("ldmatrix.sync.aligned.m8n8.x4.shared.b16 {%0,%1,%2,%3}, [%4];"
                 : "=r"(r0), "=r"(r1), "=r"(r2), "=r"(r3) : "r"(a));
}
__device__ __forceinline__ void ldsm_x4_t(uint32_t& r0, uint32_t& r1, uint32_t& r2, uint32_t& r3,
                                          uint32_t a) {
    asm volatile("ldmatrix.sync.aligned.m8n8.x4.trans.shared.b16 {%0,%1,%2,%3}, [%4];"
                 : "=r"(r0), "=r"(r1), "=r"(r2), "=r"(r3) : "r"(a));
}
__device__ __forceinline__ void cp16(uint32_t dst, const void* src) {
    asm volatile("cp.async.cg.shared.global [%0], [%1], 16;" :: "r"(dst), "l"(src) : "memory");
}
__device__ __forceinline__ void cp_commit() {
    asm volatile("cp.async.commit_group;" ::: "memory");
}
template<int N> __device__ __forceinline__ void cp_wait() {
    asm volatile("cp.async.wait_group %0;" :: "n"(N) : "memory");
}

// ---------------------------------------------------------------------------
// fp32 -> bf16 hi/lo plane converter
// ---------------------------------------------------------------------------
__global__ __launch_bounds__(256) void cvt_planes(
    const float* s0, uint32_t* h0, uint32_t* l0,
    const float* s1, uint32_t* h1, uint32_t* l1,
    const float* s2, uint32_t* h2, uint32_t* l2,
    const float* s3, uint32_t* h3, uint32_t* l3)
{
    const float* s; uint32_t *ph, *pl;
    switch (blockIdx.z) {
        case 0: s = s0; ph = h0; pl = l0; break;
        case 1: s = s1; ph = h1; pl = l1; break;
        case 2: s = s2; ph = h2; pl = l2; break;
        default: s = s3; ph = h3; pl = l3; break;
    }
    int i = blockIdx.x * 256 + threadIdx.x;
    float4 a = ((const float4*)s)[2 * i];
    float4 b = ((const float4*)s)[2 * i + 1];
    uint32_t h[4], l[4];
    cvt_pair(a.x, a.y, h[0], l[0]);
    cvt_pair(a.z, a.w, h[1], l[1]);
    cvt_pair(b.x, b.y, h[2], l[2]);
    cvt_pair(b.z, b.w, h[3], l[3]);
    ((uint4*)ph)[i] = make_uint4(h[0], h[1], h[2], h[3]);
    ((uint4*)pl)[i] = make_uint4(l[0], l[1], l[2], l[3]);
}

// ---------------------------------------------------------------------------
// Plane GEMM (unchanged from R9: cp.async 2-stage, 2 CTAs/SM)
// ---------------------------------------------------------------------------
struct GP {
    const uint32_t *Ah, *Al, *Bh, *Bl;
    const float* bias;
    float* C; uint32_t *Ph, *Pl; float scale;
};
#define GSTAGE_B 40960

__global__ __launch_bounds__(256, 2) void gemm_planes(GP a0, GP a1, GP a2, int headmode)
{
    GP g = (blockIdx.z == 0) ? a0 : (blockIdx.z == 1) ? a1 : a2;
    extern __shared__ uint32_t smg[];
    const uint32_t sb = smem_u32(smg);

    const int tid = threadIdx.x;
    const int warp = tid >> 5;
    const int lane = tid & 31;
    const int r4 = lane >> 2, q4 = lane & 3;
    const int m0w = (warp >> 2) * 64;
    const int n0w = (warp & 3) * 32;
    const int mBase = blockIdx.y * 128;
    const int nBase = blockIdx.x * 128;

    const uint32_t* srcA[4] = {
        g.Ah + (size_t)mBase * RWORDS, g.Al + (size_t)mBase * RWORDS,
        g.Bh + (size_t)nBase * RWORDS, g.Bl + (size_t)nBase * RWORDS };

    const uint32_t aOffH = (uint32_t)((m0w + (lane & 15)) * 80 + (lane >> 4) * 16);
    const uint32_t aOffL = aOffH + 10240u;
    const int bsel = lane >> 3;
    const uint32_t bOff = (uint32_t)((bsel < 2 ? 20480 : 30720) +
                                     (n0w + (lane & 7)) * 80 + (bsel & 1) * 16);

    float acc[4][4][4];
#pragma unroll
    for (int mf = 0; mf < 4; mf++)
#pragma unroll
        for (int nf = 0; nf < 4; nf++)
#pragma unroll
            for (int c = 0; c < 4; c++) acc[mf][nf][c] = 0.f;

    auto issue = [&](int stage, int ch) {
#pragma unroll
        for (int it = 0; it < 8; it++) {
            int gi = tid + it * 256;
            int pl = gi >> 9, gg = gi & 511;
            int row = gg >> 2, seg = gg & 3;
            const uint32_t* src = srcA[pl] + (size_t)row * RWORDS + ch * 16 + seg * 4;
            uint32_t dst = sb + stage * GSTAGE_B + pl * 10240 + row * 80 + seg * 16;
            cp16(dst, src);
        }
        cp_commit();
    };

    issue(0, 0);
    issue(1, 1);

    for (int ch = 0; ch < 32; ch++) {
        if (ch < 31) cp_wait<1>(); else cp_wait<0>();
        __syncthreads();
        const uint32_t sBase = sb + (ch & 1) * GSTAGE_B;

#pragma unroll
        for (int ks = 0; ks < 2; ks++) {
            const uint32_t ko = ks * 32;
            uint32_t bh[4][2], bl[4][2];
#pragma unroll
            for (int nf = 0; nf < 4; nf++)
                ldsm_x4(bh[nf][0], bh[nf][1], bl[nf][0], bl[nf][1],
                        sBase + bOff + nf * 640 + ko);
#pragma unroll
            for (int mf = 0; mf < 4; mf++) {
                uint32_t ah[4], al[4];
                ldsm_x4(ah[0], ah[1], ah[2], ah[3], sBase + aOffH + mf * 1280 + ko);
                ldsm_x4(al[0], al[1], al[2], al[3], sBase + aOffL + mf * 1280 + ko);
#pragma unroll
                for (int nf = 0; nf < 4; nf++) {
                    MMA16816(acc[mf][nf], ah, bh[nf]);
                    MMA16816(acc[mf][nf], ah, bl[nf]);
                    MMA16816(acc[mf][nf], al, bh[nf]);
                }
            }
        }
        __syncthreads();
        if (ch + 2 < 32) issue(ch & 1, ch + 2);
    }

#pragma unroll
    for (int nf = 0; nf < 4; nf++) {
        const int n = nBase + n0w + nf * 8 + q4 * 2;
        const float b0 = __ldg(g.bias + n);
        const float b1 = __ldg(g.bias + n + 1);
#pragma unroll
        for (int mf = 0; mf < 4; mf++) {
#pragma unroll
            for (int half = 0; half < 2; half++) {
                const int m = mBase + m0w + mf * 16 + r4 + half * 8;
                float v0 = (acc[mf][nf][half * 2] + b0) * g.scale;
                float v1 = (acc[mf][nf][half * 2 + 1] + b1) * g.scale;
                if (headmode) {
                    uint32_t hi, lo;
                    cvt_pair(v0, v1, hi, lo);
                    int b = m >> 11, s = m & (NS - 1);
                    int hh = n >> 6, e = n & 63;
                    size_t wo = (((size_t)((b * NH + hh) * NS + s)) * HDIM + e) >> 1;
                    g.Ph[wo] = hi;
                    g.Pl[wo] = lo;
                } else {
                    *(float2*)(g.C + (size_t)m * ND + n) = make_float2(v0, v1);
                }
            }
        }
    }
}

// ---------------------------------------------------------------------------
// Tensor-core flash attention: BQ=64, 128 threads, 2 CTAs/SM (R9 config).
// Split-3 QK^T and PV, upfront P conversion. Mask folded into S accumulator
// init (additive -9e9, numerically identical to overwrite).
// stage layout (bytes): Kh[0] Kl[9216] Vh[18432] Vl[27648]; 2 stages; maskF after.
// ---------------------------------------------------------------------------
#define KSTR 36                // u32 words per row (144B)
#define ASTAGE_B 36864         // 4 planes x 64 rows x 144B

__global__ __launch_bounds__(128, 2) void attn_mma(const uint32_t* __restrict__ qh,
                                                   const uint32_t* __restrict__ ql,
                                                   const uint32_t* __restrict__ kh,
                                                   const uint32_t* __restrict__ kl,
                                                   const uint32_t* __restrict__ vh,
                                                   const uint32_t* __restrict__ vl,
                                                   const int* __restrict__ mask,
                                                   uint32_t* __restrict__ ch_out,
                                                   uint32_t* __restrict__ cl_out)
{
    extern __shared__ uint32_t dynsm[];
    const uint32_t sb = smem_u32(dynsm);
    float* sMkF = (float*)(dynsm + 2 * (ASTAGE_B / 4));   // 64 float addends
    uint32_t* sQh = dynsm;                 // phase 1 only (64*36 words each)
    uint32_t* sQl = dynsm + 64 * KSTR;

    const int tid = threadIdx.x;
    const int warp = tid >> 5;
    const int lane = tid & 31;
    const int r4 = lane >> 2, q4 = lane & 3;
    const int qt = blockIdx.x;     // 0..31 (64-row q tiles)
    const int bh = blockIdx.y;     // 0..31
    const int b = bh >> 4, h = bh & 15;
    const size_t headW = (size_t)bh * NS * (HDIM / 2);

    // ---- Phase 1: stage Q planes (64 rows), load persistent A-frags ----
    {
        const uint32_t* pQh = qh + headW + (size_t)qt * 64 * 32;
        const uint32_t* pQl = ql + headW + (size_t)qt * 64 * 32;
#pragma unroll
        for (int it = 0; it < 8; it++) {
            int gi = tid + it * 128;       // 0..1023
            int pl = gi >> 9, gg = gi & 511;
            int row = gg >> 3, w4 = (gg & 7) * 4;
            uint4 v = *(const uint4*)((pl ? pQl : pQh) + row * 32 + w4);
            *(uint4*)((pl ? sQl : sQh) + row * KSTR + w4) = v;
        }
    }
    __syncthreads();
    uint32_t Qh[4][4], Ql[4][4];
#pragma unroll
    for (int kf = 0; kf < 4; kf++) {
        int off = (16 * warp + r4) * KSTR + 8 * kf + q4;
        Qh[kf][0] = sQh[off];              Qh[kf][1] = sQh[off + 8 * KSTR];
        Qh[kf][2] = sQh[off + 4];          Qh[kf][3] = sQh[off + 8 * KSTR + 4];
        Ql[kf][0] = sQl[off];              Ql[kf][1] = sQl[off + 8 * KSTR];
        Ql[kf][2] = sQl[off + 4];          Ql[kf][3] = sQl[off + 8 * KSTR + 4];
    }
    __syncthreads();   // stage area reusable

    const uint32_t* srcP[4] = {kh + headW, kl + headW, vh + headW, vl + headW};
    auto issue = [&](int stage, int kt) {
#pragma unroll
        for (int it = 0; it < 16; it++) {
            int gi = tid + it * 128;       // 0..2047
            int pl = gi >> 9, gg = gi & 511;
            int row = gg >> 3, seg = gg & 7;
            const uint32_t* src = srcP[pl] + (size_t)kt * 2048 + row * 32 + seg * 4;
            uint32_t dst = sb + stage * ASTAGE_B + pl * 9216 + row * 144 + seg * 16;
            cp16(dst, src);
        }
        cp_commit();
    };

    const int ksel = lane >> 3;
    const uint32_t kOff = (uint32_t)((ksel < 2 ? 0 : 9216) +
                                     (lane & 7) * 144 + (ksel & 1) * 16);
    const uint32_t vOff = (uint32_t)((lane < 16 ? 18432 : 27648) + (lane & 15) * 144);

    float O[8][4];
    float mI0 = -INFINITY, mI1 = -INFINITY, lI0 = 0.f, lI1 = 0.f;
#pragma unroll
    for (int nf = 0; nf < 8; nf++)
#pragma unroll
        for (int c = 0; c < 4; c++) O[nf][c] = 0.f;

    const int* mrow = mask + (size_t)b * NS;
    float mkldF = (tid < 64 && mrow[tid]) ? -9e9f : 0.f;

    issue(0, 0);
    issue(1, 1);

    for (int kt = 0; kt < 32; kt++) {
        if (tid < 64) sMkF[tid] = mkldF;      // safe: prev iter ended with sync
        if (kt < 31) cp_wait<1>(); else cp_wait<0>();
        __syncthreads();
        const uint32_t sStage = sb + (kt & 1) * ASTAGE_B;

        // ---- S = mask_addend + Q K^T (split-3) ----
        float S[8][4];
#pragma unroll
        for (int nf = 0; nf < 8; nf++) {
            float2 ma = *(const float2*)(sMkF + 8 * nf + 2 * q4);
            S[nf][0] = ma.x; S[nf][1] = ma.y;
            S[nf][2] = ma.x; S[nf][3] = ma.y;
        }
#pragma unroll
        for (int kf = 0; kf < 4; kf++) {
#pragma unroll
            for (int nf = 0; nf < 8; nf++) {
                uint32_t kh2[2], kl2[2];
                ldsm_x4(kh2[0], kh2[1], kl2[0], kl2[1],
                        sStage + kOff + (uint32_t)(nf * 1152 + kf * 32));
                MMA16816(S[nf], Qh[kf], kh2);
                MMA16816(S[nf], Qh[kf], kl2);
                MMA16816(S[nf], Ql[kf], kh2);
            }
        }

        // ---- online softmax (exp2 domain) ----
        float mt0 = -INFINITY, mt1 = -INFINITY;
#pragma unroll
        for (int nf = 0; nf < 8; nf++) {
            mt0 = fmaxf(mt0, fmaxf(S[nf][0], S[nf][1]));
            mt1 = fmaxf(mt1, fmaxf(S[nf][2], S[nf][3]));
        }
        mt0 = fmaxf(mt0, __shfl_xor_sync(0xffffffffu, mt0, 1));
        mt0 = fmaxf(mt0, __shfl_xor_sync(0xffffffffu, mt0, 2));
        mt1 = fmaxf(mt1, __shfl_xor_sync(0xffffffffu, mt1, 1));
        mt1 = fmaxf(mt1, __shfl_xor_sync(0xffffffffu, mt1, 2));

        float mN0 = fmaxf(mI0, mt0), mN1 = fmaxf(mI1, mt1);
        float f0 = ex2f(mI0 - mN0), f1 = ex2f(mI1 - mN1);
        float rs0 = 0.f, rs1 = 0.f;
#pragma unroll
        for (int nf = 0; nf < 8; nf++) {
            S[nf][0] = ex2f(S[nf][0] - mN0);
            S[nf][1] = ex2f(S[nf][1] - mN0);
            S[nf][2] = ex2f(S[nf][2] - mN1);
            S[nf][3] = ex2f(S[nf][3] - mN1);
            rs0 += S[nf][0] + S[nf][1];
            rs1 += S[nf][2] + S[nf][3];
        }
        rs0 += __shfl_xor_sync(0xffffffffu, rs0, 1);
        rs0 += __shfl_xor_sync(0xffffffffu, rs0, 2);
        rs1 += __shfl_xor_sync(0xffffffffu, rs1, 1);
        rs1 += __shfl_xor_sync(0xffffffffu, rs1, 2);
        lI0 = lI0 * f0 + rs0;
        lI1 = lI1 * f1 + rs1;
        mI0 = mN0; mI1 = mN1;
#pragma unroll
        for (int nf = 0; nf < 8; nf++) {
            O[nf][0] *= f0; O[nf][1] *= f0;
            O[nf][2] *= f1; O[nf][3] *= f1;
        }

        // ---- repack P into split hi/lo A-frags (upfront, for ILP) ----
        uint32_t Ph[4][4], Pl[4][4];
#pragma unroll
        for (int kf = 0; kf < 4; kf++) {
            cvt_pair(S[2*kf][0],     S[2*kf][1],     Ph[kf][0], Pl[kf][0]);
            cvt_pair(S[2*kf][2],     S[2*kf][3],     Ph[kf][1], Pl[kf][1]);
            cvt_pair(S[2*kf + 1][0], S[2*kf + 1][1], Ph[kf][2], Pl[kf][2]);
            cvt_pair(S[2*kf + 1][2], S[2*kf + 1][3], Ph[kf][3], Pl[kf][3]);
        }

        // ---- O += P V (split-3; Vhi/Vlo via one ldmatrix.x4.trans) ----
#pragma unroll
        for (int kf = 0; kf < 4; kf++) {
            uint32_t abase = sStage + vOff + (uint32_t)(kf * 2304);
#pragma unroll
            for (int nf = 0; nf < 8; nf++) {
                uint32_t vh2[2], vl2[2];
                ldsm_x4_t(vh2[0], vh2[1], vl2[0], vl2[1], abase + nf * 16);
                MMA16816(O[nf], Ph[kf], vh2);
                MMA16816(O[nf], Ph[kf], vl2);
                MMA16816(O[nf], Pl[kf], vh2);
            }
        }

        __syncthreads();
        if (kt + 2 < 32) issue(kt & 1, kt + 2);
        if (kt + 1 < 32 && tid < 64)
            mkldF = mrow[(kt + 1) * 64 + tid] ? -9e9f : 0.f;
    }

    // ---- normalize + write ctx planes [b][s][h*64+e] ----
    const float inv0 = 1.f / lI0;
    const float inv1 = 1.f / lI1;
    const int row0 = qt * 64 + 16 * warp + r4;
#pragma unroll
    for (int nf = 0; nf < 8; nf++) {
        uint32_t hi, lo;
        size_t wo0 = (((size_t)(b * NS + row0)) * ND + h * HDIM + 8 * nf + 2 * q4) >> 1;
        size_t wo1 = (((size_t)(b * NS + row0 + 8)) * ND + h * HDIM + 8 * nf + 2 * q4) >> 1;
        cvt_pair(O[nf][0] * inv0, O[nf][1] * inv0, hi, lo);
        ch_out[wo0] = hi; cl_out[wo0] = lo;
        cvt_pair(O[nf][2] * inv1, O[nf][3] * inv1, hi, lo);
        ch_out[wo1] = hi; cl_out[wo1] = lo;
    }
}

extern "C" void kernel_launch(void* const* d_in, const int* in_sizes, int n_in,
                              void* d_out, int out_size)
{
    const float* q  = (const float*)d_in[0];
    const float* k  = (const float*)d_in[1];
    const float* v  = (const float*)d_in[2];
    const int* mask = (const int*)d_in[3];
    const float* Wq = (const float*)d_in[4];
    const float* bq = (const float*)d_in[5];
    const float* Wk = (const float*)d_in[6];
    const float* bk = (const float*)d_in[7];
    const float* Wv = (const float*)d_in[8];
    const float* bv = (const float*)d_in[9];
    const float* Wo = (const float*)d_in[10];
    const float* bo = (const float*)d_in[11];
    float* out = (float*)d_out;

    uint32_t *inqh, *inql, *inkh, *inkl, *invh, *invl, *wh, *wl;
    uint32_t *qh_d, *ql_d, *kh_d, *kl_d, *vh_d, *vl_d, *ch_d, *cl_d;
    cudaGetSymbolAddress((void**)&inqh, g_inqh); cudaGetSymbolAddress((void**)&inql, g_inql);
    cudaGetSymbolAddress((void**)&inkh, g_inkh); cudaGetSymbolAddress((void**)&inkl, g_inkl);
    cudaGetSymbolAddress((void**)&invh, g_invh); cudaGetSymbolAddress((void**)&invl, g_invl);
    cudaGetSymbolAddress((void**)&wh, g_wh);     cudaGetSymbolAddress((void**)&wl, g_wl);
    cudaGetSymbolAddress((void**)&qh_d, g_qh);   cudaGetSymbolAddress((void**)&ql_d, g_ql);
    cudaGetSymbolAddress((void**)&kh_d, g_kh);   cudaGetSymbolAddress((void**)&kl_d, g_kl);
    cudaGetSymbolAddress((void**)&vh_d, g_vh);   cudaGetSymbolAddress((void**)&vl_d, g_vl);
    cudaGetSymbolAddress((void**)&ch_d, g_ch);   cudaGetSymbolAddress((void**)&cl_d, g_cl);

    const int WSTRIDE = ND * RWORDS;

    cvt_planes<<<dim3(MROWS * ND / 8 / 256, 1, 3), 256>>>(
        q, inqh, inql, k, inkh, inkl, v, invh, invl, q, inqh, inql);
    cvt_planes<<<dim3(ND * ND / 8 / 256, 1, 4), 256>>>(
        Wq, wh, wl, Wk, wh + WSTRIDE, wl + WSTRIDE,
        Wv, wh + 2 * WSTRIDE, wl + 2 * WSTRIDE, Wo, wh + 3 * WSTRIDE, wl + 3 * WSTRIDE);

    const int smem_gemm = 2 * GSTAGE_B;                 // 81920
    cudaFuncSetAttribute(gemm_planes, cudaFuncAttributeMaxDynamicSharedMemorySize, smem_gemm);
    const int smem_attn = 2 * ASTAGE_B + 64 * 4;        // 73984
    cudaFuncSetAttribute(attn_mma, cudaFuncAttributeMaxDynamicSharedMemorySize, smem_attn);

    GP aq{inqh, inql, wh, wl, bq, nullptr, qh_d, ql_d, QSCALE};
    GP ak{inkh, inkl, wh + WSTRIDE, wl + WSTRIDE, bk, nullptr, kh_d, kl_d, 1.f};
    GP av{invh, invl, wh + 2 * WSTRIDE, wl + 2 * WSTRIDE, bv, nullptr, vh_d, vl_d, 1.f};
    gemm_planes<<<dim3(ND / 128, MROWS / 128, 3), 256, smem_gemm>>>(aq, ak, av, 1);

    attn_mma<<<dim3(NS / 64, NB * NH), 128, smem_attn>>>(qh_d, ql_d, kh_d, kl_d,
                                                         vh_d, vl_d, mask, ch_d, cl_d);

    GP ao{ch_d, cl_d, wh + 3 * WSTRIDE, wl + 3 * WSTRIDE, bo, out, nullptr, nullptr, 1.f};
    gemm_planes<<<dim3(ND / 128, MROWS / 128, 1), 256, smem_gemm>>>(ao, ao, ao, 0);
}

// round 12
// speedup vs baseline: 1.0779x; 1.0032x over previous
#include <cuda_runtime.h>
#include <cuda_bf16.h>
#include <math.h>
#include <stdint.h>

#define NB 2
#define NS 2048
#define ND 1024
#define NH 16
#define HDIM 64
#define MROWS (NB*NS)
#define RWORDS (ND/2)          // 512 u32 words per 1024-elem bf16 row
#define NSPLIT 2
#define TILES_PER_SPLIT (NS / 64 / NSPLIT)   // 16

// ---- static scratch (no allocations allowed) ----
__device__ uint32_t g_inqh[MROWS*RWORDS], g_inql[MROWS*RWORDS];
__device__ uint32_t g_inkh[MROWS*RWORDS], g_inkl[MROWS*RWORDS];
__device__ uint32_t g_invh[MROWS*RWORDS], g_invl[MROWS*RWORDS];
__device__ uint32_t g_wh[4*ND*RWORDS], g_wl[4*ND*RWORDS];
__device__ uint32_t g_qh[NB*NH*NS*HDIM/2], g_ql[NB*NH*NS*HDIM/2];
__device__ uint32_t g_kh[NB*NH*NS*HDIM/2], g_kl[NB*NH*NS*HDIM/2];
__device__ uint32_t g_vh[NB*NH*NS*HDIM/2], g_vl[NB*NH*NS*HDIM/2];
__device__ uint32_t g_ch[MROWS*RWORDS], g_cl[MROWS*RWORDS];
// split-KV partials: [split][bh*32+qt][row64][col64] and (m,l) pairs
__device__ float g_pO[NSPLIT * 1024 * 64 * 64];
__device__ float g_pml[NSPLIT * 1024 * 64 * 2];

#define QSCALE 0.18033688011f      // 0.125 * log2(e)

#define MMA16816(c, a, b) \
  asm volatile("mma.sync.aligned.m16n8k16.row.col.f32.bf16.bf16.f32 " \
    "{%0,%1,%2,%3}, {%4,%5,%6,%7}, {%8,%9}, {%0,%1,%2,%3};" \
    : "+f"((c)[0]), "+f"((c)[1]), "+f"((c)[2]), "+f"((c)[3]) \
    : "r"((a)[0]), "r"((a)[1]), "r"((a)[2]), "r"((a)[3]), \
      "r"((b)[0]), "r"((b)[1]))

__device__ __forceinline__ void cvt_pair(float x, float y, uint32_t& hi, uint32_t& lo) {
    __nv_bfloat162 h = __floats2bfloat162_rn(x, y);
    float hx = __bfloat162float(__low2bfloat16(h));
    float hy = __bfloat162float(__high2bfloat16(h));
    __nv_bfloat162 l = __floats2bfloat162_rn(x - hx, y - hy);
    hi = *reinterpret_cast<uint32_t*>(&h);
    lo = *reinterpret_cast<uint32_t*>(&l);
}
__device__ __forceinline__ float ex2f(float x) {
    float y; asm("ex2.approx.ftz.f32 %0, %1;" : "=f"(y) : "f"(x)); return y;
}
__device__ __forceinline__ uint32_t smem_u32(const void* p) {
    uint32_t a;
    asm("{ .reg .u64 t; cvta.to.shared.u64 t, %1; cvt.u32.u64 %0, t; }" : "=r"(a) : "l"(p));
    return a;
}
__device__ __forceinline__ void ldsm_x4(uint32_t& r0, uint32_t& r1, uint32_t& r2, uint32_t& r3,
                                        uint32_t a) {
    asm volatile("ldmatrix.sync.aligned.m8n8.x4.shared.b16 {%0,%1,%2,%3}, [%4];"
                 : "=r"(r0), "=r"(r1), "=r"(r2), "=r"(r3) : "r"(a));
}
__device__ __forceinline__ void ldsm_x4_t(uint32_t& r0, uint32_t& r1, uint32_t& r2, uint32_t& r3,
                                          uint32_t a) {
    asm volatile("ldmatrix.sync.aligned.m8n8.x4.trans.shared.b16 {%0,%1,%2,%3}, [%4];"
                 : "=r"(r0), "=r"(r1), "=r"(r2), "=r"(r3) : "r"(a));
}
__device__ __forceinline__ void cp16(uint32_t dst, const void* src) {
    asm volatile("cp.async.cg.shared.global [%0], [%1], 16;" :: "r"(dst), "l"(src) : "memory");
}
__device__ __forceinline__ void cp_commit() {
    asm volatile("cp.async.commit_group;" ::: "memory");
}
template<int N> __device__ __forceinline__ void cp_wait() {
    asm volatile("cp.async.wait_group %0;" :: "n"(N) : "memory");
}

// ---------------------------------------------------------------------------
// fp32 -> bf16 hi/lo plane converter, 7 tensors in one launch
// ---------------------------------------------------------------------------
struct CvtArgs {
    const float* s[7];
    uint32_t* ph[7];
    uint32_t* pl[7];
    int cnt[7];          // uint4 groups per slice
};

__global__ __launch_bounds__(256) void cvt_planes7(CvtArgs a)
{
    int z = blockIdx.z;
    int i = blockIdx.x * 256 + threadIdx.x;
    if (i >= a.cnt[z]) return;
    const float* s = a.s[z];
    float4 v0 = ((const float4*)s)[2 * i];
    float4 v1 = ((const float4*)s)[2 * i + 1];
    uint32_t h[4], l[4];
    cvt_pair(v0.x, v0.y, h[0], l[0]);
    cvt_pair(v0.z, v0.w, h[1], l[1]);
    cvt_pair(v1.x, v1.y, h[2], l[2]);
    cvt_pair(v1.z, v1.w, h[3], l[3]);
    ((uint4*)a.ph[z])[i] = make_uint4(h[0], h[1], h[2], h[3]);
    ((uint4*)a.pl[z])[i] = make_uint4(l[0], l[1], l[2], l[3]);
}

// ---------------------------------------------------------------------------
// Plane GEMM (unchanged from R9: cp.async 2-stage, 2 CTAs/SM)
// ---------------------------------------------------------------------------
struct GP {
    const uint32_t *Ah, *Al, *Bh, *Bl;
    const float* bias;
    float* C; uint32_t *Ph, *Pl; float scale;
};
#define GSTAGE_B 40960

__global__ __launch_bounds__(256, 2) void gemm_planes(GP a0, GP a1, GP a2, int headmode)
{
    GP g = (blockIdx.z == 0) ? a0 : (blockIdx.z == 1) ? a1 : a2;
    extern __shared__ uint32_t smg[];
    const uint32_t sb = smem_u32(smg);

    const int tid = threadIdx.x;
    const int warp = tid >> 5;
    const int lane = tid & 31;
    const int r4 = lane >> 2, q4 = lane & 3;
    const int m0w = (warp >> 2) * 64;
    const int n0w = (warp & 3) * 32;
    const int mBase = blockIdx.y * 128;
    const int nBase = blockIdx.x * 128;

    const uint32_t* srcA[4] = {
        g.Ah + (size_t)mBase * RWORDS, g.Al + (size_t)mBase * RWORDS,
        g.Bh + (size_t)nBase * RWORDS, g.Bl + (size_t)nBase * RWORDS };

    const uint32_t aOffH = (uint32_t)((m0w + (lane & 15)) * 80 + (lane >> 4) * 16);
    const uint32_t aOffL = aOffH + 10240u;
    const int bsel = lane >> 3;
    const uint32_t bOff = (uint32_t)((bsel < 2 ? 20480 : 30720) +
                                     (n0w + (lane & 7)) * 80 + (bsel & 1) * 16);

    float acc[4][4][4];
#pragma unroll
    for (int mf = 0; mf < 4; mf++)
#pragma unroll
        for (int nf = 0; nf < 4; nf++)
#pragma unroll
            for (int c = 0; c < 4; c++) acc[mf][nf][c] = 0.f;

    auto issue = [&](int stage, int ch) {
#pragma unroll
        for (int it = 0; it < 8; it++) {
            int gi = tid + it * 256;
            int pl = gi >> 9, gg = gi & 511;
            int row = gg >> 2, seg = gg & 3;
            const uint32_t* src = srcA[pl] + (size_t)row * RWORDS + ch * 16 + seg * 4;
            uint32_t dst = sb + stage * GSTAGE_B + pl * 10240 + row * 80 + seg * 16;
            cp16(dst, src);
        }
        cp_commit();
    };

    issue(0, 0);
    issue(1, 1);

    for (int ch = 0; ch < 32; ch++) {
        if (ch < 31) cp_wait<1>(); else cp_wait<0>();
        __syncthreads();
        const uint32_t sBase = sb + (ch & 1) * GSTAGE_B;

#pragma unroll
        for (int ks = 0; ks < 2; ks++) {
            const uint32_t ko = ks * 32;
            uint32_t bh[4][2], bl[4][2];
#pragma unroll
            for (int nf = 0; nf < 4; nf++)
                ldsm_x4(bh[nf][0], bh[nf][1], bl[nf][0], bl[nf][1],
                        sBase + bOff + nf * 640 + ko);
#pragma unroll
            for (int mf = 0; mf < 4; mf++) {
                uint32_t ah[4], al[4];
                ldsm_x4(ah[0], ah[1], ah[2], ah[3], sBase + aOffH + mf * 1280 + ko);
                ldsm_x4(al[0], al[1], al[2], al[3], sBase + aOffL + mf * 1280 + ko);
#pragma unroll
                for (int nf = 0; nf < 4; nf++) {
                    MMA16816(acc[mf][nf], ah, bh[nf]);
                    MMA16816(acc[mf][nf], ah, bl[nf]);
                    MMA16816(acc[mf][nf], al, bh[nf]);
                }
            }
        }
        __syncthreads();
        if (ch + 2 < 32) issue(ch & 1, ch + 2);
    }

#pragma unroll
    for (int nf = 0; nf < 4; nf++) {
        const int n = nBase + n0w + nf * 8 + q4 * 2;
        const float b0 = __ldg(g.bias + n);
        const float b1 = __ldg(g.bias + n + 1);
#pragma unroll
        for (int mf = 0; mf < 4; mf++) {
#pragma unroll
            for (int half = 0; half < 2; half++) {
                const int m = mBase + m0w + mf * 16 + r4 + half * 8;
                float v0 = (acc[mf][nf][half * 2] + b0) * g.scale;
                float v1 = (acc[mf][nf][half * 2 + 1] + b1) * g.scale;
                if (headmode) {
                    uint32_t hi, lo;
                    cvt_pair(v0, v1, hi, lo);
                    int b = m >> 11, s = m & (NS - 1);
                    int hh = n >> 6, e = n & 63;
                    size_t wo = (((size_t)((b * NH + hh) * NS + s)) * HDIM + e) >> 1;
                    g.Ph[wo] = hi;
                    g.Pl[wo] = lo;
                } else {
                    *(float2*)(g.C + (size_t)m * ND + n) = make_float2(v0, v1);
                }
            }
        }
    }
}

// ---------------------------------------------------------------------------
// Tensor-core flash attention, split-KV x2: BQ=64, 128 threads, 2 CTAs/SM.
// Each split handles 16 KV tiles; writes UNNORMALIZED partial O + (m,l).
// Split-3 QK^T and PV, upfront P conversion, additive mask.
// ---------------------------------------------------------------------------
#define KSTR 36                // u32 words per row (144B)
#define ASTAGE_B 36864         // 4 planes x 64 rows x 144B

__global__ __launch_bounds__(128, 2) void attn_mma(const uint32_t* __restrict__ qh,
                                                   const uint32_t* __restrict__ ql,
                                                   const uint32_t* __restrict__ kh,
                                                   const uint32_t* __restrict__ kl,
                                                   const uint32_t* __restrict__ vh,
                                                   const uint32_t* __restrict__ vl,
                                                   const int* __restrict__ mask,
                                                   float* __restrict__ pO,
                                                   float* __restrict__ pml)
{
    extern __shared__ uint32_t dynsm[];
    const uint32_t sb = smem_u32(dynsm);
    float* sMkF = (float*)(dynsm + 2 * (ASTAGE_B / 4));   // 64 float addends
    uint32_t* sQh = dynsm;                 // phase 1 only (64*36 words each)
    uint32_t* sQl = dynsm + 64 * KSTR;

    const int tid = threadIdx.x;
    const int warp = tid >> 5;
    const int lane = tid & 31;
    const int r4 = lane >> 2, q4 = lane & 3;
    const int qt = blockIdx.x;     // 0..31 (64-row q tiles)
    const int bh = blockIdx.y;     // 0..31
    const int sp = blockIdx.z;     // 0..1 (kv split)
    const int b = bh >> 4;
    const int ktBase = sp * TILES_PER_SPLIT;
    const size_t headW = (size_t)bh * NS * (HDIM / 2);

    // ---- Phase 1: stage Q planes (64 rows), load persistent A-frags ----
    {
        const uint32_t* pQh = qh + headW + (size_t)qt * 64 * 32;
        const uint32_t* pQl = ql + headW + (size_t)qt * 64 * 32;
#pragma unroll
        for (int it = 0; it < 8; it++) {
            int gi = tid + it * 128;       // 0..1023
            int pl = gi >> 9, gg = gi & 511;
            int row = gg >> 3, w4 = (gg & 7) * 4;
            uint4 v = *(const uint4*)((pl ? pQl : pQh) + row * 32 + w4);
            *(uint4*)((pl ? sQl : sQh) + row * KSTR + w4) = v;
        }
    }
    __syncthreads();
    uint32_t Qh[4][4], Ql[4][4];
#pragma unroll
    for (int kf = 0; kf < 4; kf++) {
        int off = (16 * warp + r4) * KSTR + 8 * kf + q4;
        Qh[kf][0] = sQh[off];              Qh[kf][1] = sQh[off + 8 * KSTR];
        Qh[kf][2] = sQh[off + 4];          Qh[kf][3] = sQh[off + 8 * KSTR + 4];
        Ql[kf][0] = sQl[off];              Ql[kf][1] = sQl[off + 8 * KSTR];
        Ql[kf][2] = sQl[off + 4];          Ql[kf][3] = sQl[off + 8 * KSTR + 4];
    }
    __syncthreads();   // stage area reusable

    const uint32_t* srcP[4] = {kh + headW, kl + headW, vh + headW, vl + headW};
    auto issue = [&](int stage, int kt) {
#pragma unroll
        for (int it = 0; it < 16; it++) {
            int gi = tid + it * 128;       // 0..2047
            int pl = gi >> 9, gg = gi & 511;
            int row = gg >> 3, seg = gg & 7;
            const uint32_t* src = srcP[pl] + (size_t)kt * 2048 + row * 32 + seg * 4;
            uint32_t dst = sb + stage * ASTAGE_B + pl * 9216 + row * 144 + seg * 16;
            cp16(dst, src);
        }
        cp_commit();
    };

    const int ksel = lane >> 3;
    const uint32_t kOff = (uint32_t)((ksel < 2 ? 0 : 9216) +
                                     (lane & 7) * 144 + (ksel & 1) * 16);
    const uint32_t vOff = (uint32_t)((lane < 16 ? 18432 : 27648) + (lane & 15) * 144);

    float O[8][4];
    float mI0 = -INFINITY, mI1 = -INFINITY, lI0 = 0.f, lI1 = 0.f;
#pragma unroll
    for (int nf = 0; nf < 8; nf++)
#pragma unroll
        for (int c = 0; c < 4; c++) O[nf][c] = 0.f;

    const int* mrow = mask + (size_t)b * NS;
    float mkldF = (tid < 64 && mrow[ktBase * 64 + tid]) ? -9e9f : 0.f;

    issue(0, ktBase);
    issue(1, ktBase + 1);

    for (int t = 0; t < TILES_PER_SPLIT; t++) {
        const int kt = ktBase + t;
        if (tid < 64) sMkF[tid] = mkldF;      // safe: prev iter ended with sync
        if (t < TILES_PER_SPLIT - 1) cp_wait<1>(); else cp_wait<0>();
        __syncthreads();
        const uint32_t sStage = sb + (t & 1) * ASTAGE_B;

        // ---- S = mask_addend + Q K^T (split-3) ----
        float S[8][4];
#pragma unroll
        for (int nf = 0; nf < 8; nf++) {
            float2 ma = *(const float2*)(sMkF + 8 * nf + 2 * q4);
            S[nf][0] = ma.x; S[nf][1] = ma.y;
            S[nf][2] = ma.x; S[nf][3] = ma.y;
        }
#pragma unroll
        for (int kf = 0; kf < 4; kf++) {
#pragma unroll
            for (int nf = 0; nf < 8; nf++) {
                uint32_t kh2[2], kl2[2];
                ldsm_x4(kh2[0], kh2[1], kl2[0], kl2[1],
                        sStage + kOff + (uint32_t)(nf * 1152 + kf * 32));
                MMA16816(S[nf], Qh[kf], kh2);
                MMA16816(S[nf], Qh[kf], kl2);
                MMA16816(S[nf], Ql[kf], kh2);
            }
        }

        // ---- online softmax (exp2 domain) ----
        float mt0 = -INFINITY, mt1 = -INFINITY;
#pragma unroll
        for (int nf = 0; nf < 8; nf++) {
            mt0 = fmaxf(mt0, fmaxf(S[nf][0], S[nf][1]));
            mt1 = fmaxf(mt1, fmaxf(S[nf][2], S[nf][3]));
        }
        mt0 = fmaxf(mt0, __shfl_xor_sync(0xffffffffu, mt0, 1));
        mt0 = fmaxf(mt0, __shfl_xor_sync(0xffffffffu, mt0, 2));
        mt1 = fmaxf(mt1, __shfl_xor_sync(0xffffffffu, mt1, 1));
        mt1 = fmaxf(mt1, __shfl_xor_sync(0xffffffffu, mt1, 2));

        float mN0 = fmaxf(mI0, mt0), mN1 = fmaxf(mI1, mt1);
        float f0 = ex2f(mI0 - mN0), f1 = ex2f(mI1 - mN1);
        float rs0 = 0.f, rs1 = 0.f;
#pragma unroll
        for (int nf = 0; nf < 8; nf++) {
            S[nf][0] = ex2f(S[nf][0] - mN0);
            S[nf][1] = ex2f(S[nf][1] - mN0);
            S[nf][2] = ex2f(S[nf][2] - mN1);
            S[nf][3] = ex2f(S[nf][3] - mN1);
            rs0 += S[nf][0] + S[nf][1];
            rs1 += S[nf][2] + S[nf][3];
        }
        rs0 += __shfl_xor_sync(0xffffffffu, rs0, 1);
        rs0 += __shfl_xor_sync(0xffffffffu, rs0, 2);
        rs1 += __shfl_xor_sync(0xffffffffu, rs1, 1);
        rs1 += __shfl_xor_sync(0xffffffffu, rs1, 2);
        lI0 = lI0 * f0 + rs0;
        lI1 = lI1 * f1 + rs1;
        mI0 = mN0; mI1 = mN1;
#pragma unroll
        for (int nf = 0; nf < 8; nf++) {
            O[nf][0] *= f0; O[nf][1] *= f0;
            O[nf][2] *= f1; O[nf][3] *= f1;
        }

        // ---- repack P into split hi/lo A-frags (upfront, for ILP) ----
        uint32_t Ph[4][4], Pl[4][4];
#pragma unroll
        for (int kf = 0; kf < 4; kf++) {
            cvt_pair(S[2*kf][0],     S[2*kf][1],     Ph[kf][0], Pl[kf][0]);
            cvt_pair(S[2*kf][2],     S[2*kf][3],     Ph[kf][1], Pl[kf][1]);
            cvt_pair(S[2*kf + 1][0], S[2*kf + 1][1], Ph[kf][2], Pl[kf][2]);
            cvt_pair(S[2*kf + 1][2], S[2*kf + 1][3], Ph[kf][3], Pl[kf][3]);
        }

        // ---- O += P V (split-3; Vhi/Vlo via one ldmatrix.x4.trans) ----
#pragma unroll
        for (int kf = 0; kf < 4; kf++) {
            uint32_t abase = sStage + vOff + (uint32_t)(kf * 2304);
#pragma unroll
            for (int nf = 0; nf < 8; nf++) {
                uint32_t vh2[2], vl2[2];
                ldsm_x4_t(vh2[0], vh2[1], vl2[0], vl2[1], abase + nf * 16);
                MMA16816(O[nf], Ph[kf], vh2);
                MMA16816(O[nf], Ph[kf], vl2);
                MMA16816(O[nf], Pl[kf], vh2);
            }
        }

        __syncthreads();
        if (t + 2 < TILES_PER_SPLIT) issue(t & 1, kt + 2);
        if (t + 1 < TILES_PER_SPLIT && tid < 64)
            mkldF = mrow[(kt + 1) * 64 + tid] ? -9e9f : 0.f;
    }

    // ---- write UNNORMALIZED partials + (m,l) ----
    const int tile = bh * 32 + qt;
    float* po = pO + (size_t)sp * (1024 * 64 * 64) + (size_t)tile * (64 * 64);
    float* pm = pml + (size_t)sp * (1024 * 64 * 2) + (size_t)tile * (64 * 2);
    const int row0 = 16 * warp + r4;
#pragma unroll
    for (int nf = 0; nf < 8; nf++) {
        *(float2*)(po + row0 * 64 + 8 * nf + 2 * q4)       = make_float2(O[nf][0], O[nf][1]);
        *(float2*)(po + (row0 + 8) * 64 + 8 * nf + 2 * q4) = make_float2(O[nf][2], O[nf][3]);
    }
    if (q4 == 0) {
        *(float2*)(pm + row0 * 2)       = make_float2(mI0, lI0);
        *(float2*)(pm + (row0 + 8) * 2) = make_float2(mI1, lI1);
    }
}

// ---------------------------------------------------------------------------
// Combine split-KV partials -> ctx bf16 planes [b][s][h*64+e]
// One thread handles 16 cols of one row. 262144 threads.
// ---------------------------------------------------------------------------
__global__ __launch_bounds__(256) void attn_combine(const float* __restrict__ pO,
                                                    const float* __restrict__ pml,
                                                    uint32_t* __restrict__ ch_out,
                                                    uint32_t* __restrict__ cl_out)
{
    const int gid = blockIdx.x * 256 + threadIdx.x;   // 0..262143
    const int grp = gid & 3;
    const int rowg = gid >> 2;      // tile*64 + r
    const int r = rowg & 63;
    const int tile = rowg >> 6;     // bh*32 + qt
    const int qt = tile & 31, bh = tile >> 5;
    const size_t SPO = (size_t)1024 * 64 * 64;
    const size_t SPM = (size_t)1024 * 64 * 2;
    const size_t obase = (size_t)rowg * 64 + grp * 16;
    const size_t mlbase = (size_t)rowg * 2;

    float2 ml0 = *(const float2*)(pml + mlbase);
    float2 ml1 = *(const float2*)(pml + SPM + mlbase);
    float m = fmaxf(ml0.x, ml1.x);
    float f0 = ex2f(ml0.x - m), f1 = ex2f(ml1.x - m);
    float inv = 1.f / (ml0.y * f0 + ml1.y * f1);
    f0 *= inv; f1 *= inv;

    uint32_t hw[8], lw[8];
#pragma unroll
    for (int c4 = 0; c4 < 4; c4++) {
        float4 a = *(const float4*)(pO + obase + c4 * 4);
        float4 bb = *(const float4*)(pO + SPO + obase + c4 * 4);
        float o0 = a.x * f0 + bb.x * f1;
        float o1 = a.y * f0 + bb.y * f1;
        float o2 = a.z * f0 + bb.z * f1;
        float o3 = a.w * f0 + bb.w * f1;
        cvt_pair(o0, o1, hw[c4 * 2], lw[c4 * 2]);
        cvt_pair(o2, o3, hw[c4 * 2 + 1], lw[c4 * 2 + 1]);
    }

    const int b = bh >> 4, h = bh & 15;
    const int srow = qt * 64 + r;
    const size_t wo = (((size_t)(b * NS + srow)) * ND + h * HDIM + grp * 16) >> 1;
    *(uint4*)(ch_out + wo)     = make_uint4(hw[0], hw[1], hw[2], hw[3]);
    *(uint4*)(ch_out + wo + 4) = make_uint4(hw[4], hw[5], hw[6], hw[7]);
    *(uint4*)(cl_out + wo)     = make_uint4(lw[0], lw[1], lw[2], lw[3]);
    *(uint4*)(cl_out + wo + 4) = make_uint4(lw[4], lw[5], lw[6], lw[7]);
}

extern "C" void kernel_launch(void* const* d_in, const int* in_sizes, int n_in,
                              void* d_out, int out_size)
{
    const float* q  = (const float*)d_in[0];
    const float* k  = (const float*)d_in[1];
    const float* v  = (const float*)d_in[2];
    const int* mask = (const int*)d_in[3];
    const float* Wq = (const float*)d_in[4];
    const float* bq = (const float*)d_in[5];
    const float* Wk = (const float*)d_in[6];
    const float* bk = (const float*)d_in[7];
    const float* Wv = (const float*)d_in[8];
    const float* bv = (const float*)d_in[9];
    const float* Wo = (const float*)d_in[10];
    const float* bo = (const float*)d_in[11];
    float* out = (float*)d_out;

    uint32_t *inqh, *inql, *inkh, *inkl, *invh, *invl, *wh, *wl;
    uint32_t *qh_d, *ql_d, *kh_d, *kl_d, *vh_d, *vl_d, *ch_d, *cl_d;
    float *pO_d, *pml_d;
    cudaGetSymbolAddress((void**)&inqh, g_inqh); cudaGetSymbolAddress((void**)&inql, g_inql);
    cudaGetSymbolAddress((void**)&inkh, g_inkh); cudaGetSymbolAddress((void**)&inkl, g_inkl);
    cudaGetSymbolAddress((void**)&invh, g_invh); cudaGetSymbolAddress((void**)&invl, g_invl);
    cudaGetSymbolAddress((void**)&wh, g_wh);     cudaGetSymbolAddress((void**)&wl, g_wl);
    cudaGetSymbolAddress((void**)&qh_d, g_qh);   cudaGetSymbolAddress((void**)&ql_d, g_ql);
    cudaGetSymbolAddress((void**)&kh_d, g_kh);   cudaGetSymbolAddress((void**)&kl_d, g_kl);
    cudaGetSymbolAddress((void**)&vh_d, g_vh);   cudaGetSymbolAddress((void**)&vl_d, g_vl);
    cudaGetSymbolAddress((void**)&ch_d, g_ch);   cudaGetSymbolAddress((void**)&cl_d, g_cl);
    cudaGetSymbolAddress((void**)&pO_d, g_pO);   cudaGetSymbolAddress((void**)&pml_d, g_pml);

    const int WSTRIDE = ND * RWORDS;
    const int NIN = MROWS * ND / 8;    // 524288 uint4 groups per input tensor
    const int NW  = ND * ND / 8;       // 131072 per weight tensor

    // 1+2) convert inputs + weights in ONE launch (7 z-slices)
    CvtArgs ca;
    ca.s[0] = q;  ca.ph[0] = inqh; ca.pl[0] = inql; ca.cnt[0] = NIN;
    ca.s[1] = k;  ca.ph[1] = inkh; ca.pl[1] = inkl; ca.cnt[1] = NIN;
    ca.s[2] = v;  ca.ph[2] = invh; ca.pl[2] = invl; ca.cnt[2] = NIN;
    ca.s[3] = Wq; ca.ph[3] = wh;                ca.pl[3] = wl;                ca.cnt[3] = NW;
    ca.s[4] = Wk; ca.ph[4] = wh + WSTRIDE;      ca.pl[4] = wl + WSTRIDE;      ca.cnt[4] = NW;
    ca.s[5] = Wv; ca.ph[5] = wh + 2 * WSTRIDE;  ca.pl[5] = wl + 2 * WSTRIDE;  ca.cnt[5] = NW;
    ca.s[6] = Wo; ca.ph[6] = wh + 3 * WSTRIDE;  ca.pl[6] = wl + 3 * WSTRIDE;  ca.cnt[6] = NW;
    cvt_planes7<<<dim3((NIN + 255) / 256, 1, 7), 256>>>(ca);

    const int smem_gemm = 2 * GSTAGE_B;                 // 81920
    cudaFuncSetAttribute(gemm_planes, cudaFuncAttributeMaxDynamicSharedMemorySize, smem_gemm);
    const int smem_attn = 2 * ASTAGE_B + 64 * 4;        // 73984
    cudaFuncSetAttribute(attn_mma, cudaFuncAttributeMaxDynamicSharedMemorySize, smem_attn);

    // 3) QKV projections -> head planes (Q pre-scaled)
    GP aq{inqh, inql, wh, wl, bq, nullptr, qh_d, ql_d, QSCALE};
    GP ak{inkh, inkl, wh + WSTRIDE, wl + WSTRIDE, bk, nullptr, kh_d, kl_d, 1.f};
    GP av{invh, invl, wh + 2 * WSTRIDE, wl + 2 * WSTRIDE, bv, nullptr, vh_d, vl_d, 1.f};
    gemm_planes<<<dim3(ND / 128, MROWS / 128, 3), 256, smem_gemm>>>(aq, ak, av, 1);

    // 4) attention split-KV x2 -> partials
    attn_mma<<<dim3(NS / 64, NB * NH, NSPLIT), 128, smem_attn>>>(
        qh_d, ql_d, kh_d, kl_d, vh_d, vl_d, mask, pO_d, pml_d);

    // 5) combine partials -> ctx planes
    attn_combine<<<1024, 256>>>(pO_d, pml_d, ch_d, cl_d);

    // 6) output projection (fp32 out)
    GP ao{ch_d, cl_d, wh + 3 * WSTRIDE, wl + 3 * WSTRIDE, bo, out, nullptr, nullptr, 1.f};
    gemm_planes<<<dim3(ND / 128, MROWS / 128, 1), 256, smem_gemm>>>(ao, ao, ao, 0);
}

// round 13
// speedup vs baseline: 1.4436x; 1.3392x over previous
#include <cuda_runtime.h>
#include <cuda_bf16.h>
#include <cuda_fp16.h>
#include <math.h>
#include <stdint.h>

#define NB 2
#define NS 2048
#define ND 1024
#define NH 16
#define HDIM 64
#define MROWS (NB*NS)
#define RWORDS (ND/2)          // 512 u32 words per 1024-elem bf16 row
#define NSPLIT 2
#define TILES_PER_SPLIT (NS / 64 / NSPLIT)   // 16

// ---- static scratch (no allocations allowed) ----
__device__ uint32_t g_inqh[MROWS*RWORDS], g_inql[MROWS*RWORDS];
__device__ uint32_t g_inkh[MROWS*RWORDS], g_inkl[MROWS*RWORDS];
__device__ uint32_t g_invh[MROWS*RWORDS], g_invl[MROWS*RWORDS];
__device__ uint32_t g_wh[4*ND*RWORDS], g_wl[4*ND*RWORDS];
// fp16 single planes for q/k/v in head layout [b*H+h][s][e] (1 u32 = 2 halfs)
__device__ uint32_t g_qf[NB*NH*NS*HDIM/2];
__device__ uint32_t g_kf[NB*NH*NS*HDIM/2];
__device__ uint32_t g_vf[NB*NH*NS*HDIM/2];
// ctx bf16 hi/lo planes [b][s][h*64+e]
__device__ uint32_t g_ch[MROWS*RWORDS], g_cl[MROWS*RWORDS];
// split-KV partials
__device__ float g_pO[NSPLIT * 1024 * 64 * 64];
__device__ float g_pml[NSPLIT * 1024 * 64 * 2];

#define QSCALE 0.18033688011f      // 0.125 * log2(e)

#define MMA16816(c, a, b) \
  asm volatile("mma.sync.aligned.m16n8k16.row.col.f32.bf16.bf16.f32 " \
    "{%0,%1,%2,%3}, {%4,%5,%6,%7}, {%8,%9}, {%0,%1,%2,%3};" \
    : "+f"((c)[0]), "+f"((c)[1]), "+f"((c)[2]), "+f"((c)[3]) \
    : "r"((a)[0]), "r"((a)[1]), "r"((a)[2]), "r"((a)[3]), \
      "r"((b)[0]), "r"((b)[1]))

#define MMAH16816(c, a, b) \
  asm volatile("mma.sync.aligned.m16n8k16.row.col.f32.f16.f16.f32 " \
    "{%0,%1,%2,%3}, {%4,%5,%6,%7}, {%8,%9}, {%0,%1,%2,%3};" \
    : "+f"((c)[0]), "+f"((c)[1]), "+f"((c)[2]), "+f"((c)[3]) \
    : "r"((a)[0]), "r"((a)[1]), "r"((a)[2]), "r"((a)[3]), \
      "r"((b)[0]), "r"((b)[1]))

__device__ __forceinline__ void cvt_pair(float x, float y, uint32_t& hi, uint32_t& lo) {
    __nv_bfloat162 h = __floats2bfloat162_rn(x, y);
    float hx = __bfloat162float(__low2bfloat16(h));
    float hy = __bfloat162float(__high2bfloat16(h));
    __nv_bfloat162 l = __floats2bfloat162_rn(x - hx, y - hy);
    hi = *reinterpret_cast<uint32_t*>(&h);
    lo = *reinterpret_cast<uint32_t*>(&l);
}
__device__ __forceinline__ uint32_t pack_h2(float x, float y) {
    __half2 h = __floats2half2_rn(x, y);
    return *reinterpret_cast<uint32_t*>(&h);
}
__device__ __forceinline__ float ex2f(float x) {
    float y; asm("ex2.approx.ftz.f32 %0, %1;" : "=f"(y) : "f"(x)); return y;
}
__device__ __forceinline__ uint32_t smem_u32(const void* p) {
    uint32_t a;
    asm("{ .reg .u64 t; cvta.to.shared.u64 t, %1; cvt.u32.u64 %0, t; }" : "=r"(a) : "l"(p));
    return a;
}
__device__ __forceinline__ void ldsm_x4(uint32_t& r0, uint32_t& r1, uint32_t& r2, uint32_t& r3,
                                        uint32_t a) {
    asm volatile("ldmatrix.sync.aligned.m8n8.x4.shared.b16 {%0,%1,%2,%3}, [%4];"
                 : "=r"(r0), "=r"(r1), "=r"(r2), "=r"(r3) : "r"(a));
}
__device__ __forceinline__ void ldsm_x4_t(uint32_t& r0, uint32_t& r1, uint32_t& r2, uint32_t& r3,
                                          uint32_t a) {
    asm volatile("ldmatrix.sync.aligned.m8n8.x4.trans.shared.b16 {%0,%1,%2,%3}, [%4];"
                 : "=r"(r0), "=r"(r1), "=r"(r2), "=r"(r3) : "r"(a));
}
__device__ __forceinline__ void cp16(uint32_t dst, const void* src) {
    asm volatile("cp.async.cg.shared.global [%0], [%1], 16;" :: "r"(dst), "l"(src) : "memory");
}
__device__ __forceinline__ void cp_commit() {
    asm volatile("cp.async.commit_group;" ::: "memory");
}
template<int N> __device__ __forceinline__ void cp_wait() {
    asm volatile("cp.async.wait_group %0;" :: "n"(N) : "memory");
}

// ---------------------------------------------------------------------------
// fp32 -> bf16 hi/lo plane converter, 7 tensors in one launch
// ---------------------------------------------------------------------------
struct CvtArgs {
    const float* s[7];
    uint32_t* ph[7];
    uint32_t* pl[7];
    int cnt[7];
};

__global__ __launch_bounds__(256) void cvt_planes7(CvtArgs a)
{
    int z = blockIdx.z;
    int i = blockIdx.x * 256 + threadIdx.x;
    if (i >= a.cnt[z]) return;
    const float* s = a.s[z];
    float4 v0 = ((const float4*)s)[2 * i];
    float4 v1 = ((const float4*)s)[2 * i + 1];
    uint32_t h[4], l[4];
    cvt_pair(v0.x, v0.y, h[0], l[0]);
    cvt_pair(v0.z, v0.w, h[1], l[1]);
    cvt_pair(v1.x, v1.y, h[2], l[2]);
    cvt_pair(v1.z, v1.w, h[3], l[3]);
    ((uint4*)a.ph[z])[i] = make_uint4(h[0], h[1], h[2], h[3]);
    ((uint4*)a.pl[z])[i] = make_uint4(l[0], l[1], l[2], l[3]);
}

// ---------------------------------------------------------------------------
// Plane GEMM (cp.async 2-stage, 2 CTAs/SM). split-3 bf16.
// headmode=1: write (acc+bias)*scale as ONE fp16 plane in head layout.
// headmode=0: fp32 row-major.
// ---------------------------------------------------------------------------
struct GP {
    const uint32_t *Ah, *Al, *Bh, *Bl;
    const float* bias;
    float* C; uint32_t *Pf; float scale;
};
#define GSTAGE_B 40960

__global__ __launch_bounds__(256, 2) void gemm_planes(GP a0, GP a1, GP a2, int headmode)
{
    GP g = (blockIdx.z == 0) ? a0 : (blockIdx.z == 1) ? a1 : a2;
    extern __shared__ uint32_t smg[];
    const uint32_t sb = smem_u32(smg);

    const int tid = threadIdx.x;
    const int warp = tid >> 5;
    const int lane = tid & 31;
    const int r4 = lane >> 2, q4 = lane & 3;
    const int m0w = (warp >> 2) * 64;
    const int n0w = (warp & 3) * 32;
    const int mBase = blockIdx.y * 128;
    const int nBase = blockIdx.x * 128;

    const uint32_t* srcA[4] = {
        g.Ah + (size_t)mBase * RWORDS, g.Al + (size_t)mBase * RWORDS,
        g.Bh + (size_t)nBase * RWORDS, g.Bl + (size_t)nBase * RWORDS };

    const uint32_t aOffH = (uint32_t)((m0w + (lane & 15)) * 80 + (lane >> 4) * 16);
    const uint32_t aOffL = aOffH + 10240u;
    const int bsel = lane >> 3;
    const uint32_t bOff = (uint32_t)((bsel < 2 ? 20480 : 30720) +
                                     (n0w + (lane & 7)) * 80 + (bsel & 1) * 16);

    float acc[4][4][4];
#pragma unroll
    for (int mf = 0; mf < 4; mf++)
#pragma unroll
        for (int nf = 0; nf < 4; nf++)
#pragma unroll
            for (int c = 0; c < 4; c++) acc[mf][nf][c] = 0.f;

    auto issue = [&](int stage, int ch) {
#pragma unroll
        for (int it = 0; it < 8; it++) {
            int gi = tid + it * 256;
            int pl = gi >> 9, gg = gi & 511;
            int row = gg >> 2, seg = gg & 3;
            const uint32_t* src = srcA[pl] + (size_t)row * RWORDS + ch * 16 + seg * 4;
            uint32_t dst = sb + stage * GSTAGE_B + pl * 10240 + row * 80 + seg * 16;
            cp16(dst, src);
        }
        cp_commit();
    };

    issue(0, 0);
    issue(1, 1);

    for (int ch = 0; ch < 32; ch++) {
        if (ch < 31) cp_wait<1>(); else cp_wait<0>();
        __syncthreads();
        const uint32_t sBase = sb + (ch & 1) * GSTAGE_B;

#pragma unroll
        for (int ks = 0; ks < 2; ks++) {
            const uint32_t ko = ks * 32;
            uint32_t bh[4][2], bl[4][2];
#pragma unroll
            for (int nf = 0; nf < 4; nf++)
                ldsm_x4(bh[nf][0], bh[nf][1], bl[nf][0], bl[nf][1],
                        sBase + bOff + nf * 640 + ko);
#pragma unroll
            for (int mf = 0; mf < 4; mf++) {
                uint32_t ah[4], al[4];
                ldsm_x4(ah[0], ah[1], ah[2], ah[3], sBase + aOffH + mf * 1280 + ko);
                ldsm_x4(al[0], al[1], al[2], al[3], sBase + aOffL + mf * 1280 + ko);
#pragma unroll
                for (int nf = 0; nf < 4; nf++) {
                    MMA16816(acc[mf][nf], ah, bh[nf]);
                    MMA16816(acc[mf][nf], ah, bl[nf]);
                    MMA16816(acc[mf][nf], al, bh[nf]);
                }
            }
        }
        __syncthreads();
        if (ch + 2 < 32) issue(ch & 1, ch + 2);
    }

#pragma unroll
    for (int nf = 0; nf < 4; nf++) {
        const int n = nBase + n0w + nf * 8 + q4 * 2;
        const float b0 = __ldg(g.bias + n);
        const float b1 = __ldg(g.bias + n + 1);
#pragma unroll
        for (int mf = 0; mf < 4; mf++) {
#pragma unroll
            for (int half = 0; half < 2; half++) {
                const int m = mBase + m0w + mf * 16 + r4 + half * 8;
                float v0 = (acc[mf][nf][half * 2] + b0) * g.scale;
                float v1 = (acc[mf][nf][half * 2 + 1] + b1) * g.scale;
                if (headmode) {
                    int b = m >> 11, s = m & (NS - 1);
                    int hh = n >> 6, e = n & 63;
                    size_t wo = (((size_t)((b * NH + hh) * NS + s)) * HDIM + e) >> 1;
                    g.Pf[wo] = pack_h2(v0, v1);
                } else {
                    *(float2*)(g.C + (size_t)m * ND + n) = make_float2(v0, v1);
                }
            }
        }
    }
}

// ---------------------------------------------------------------------------
// fp16 tensor-core flash attention, split-KV x2: BQ=64, 128 threads, 3 CTAs/SM.
// Single-pass fp16 QK^T and PV (operand rounding 2^-11; products exact).
// Additive mask, exp2-domain softmax, unnormalized partial outputs.
// stage (bytes): Kf[0..9215] Vf[9216..18431]; 2 stages; maskF after.
// ---------------------------------------------------------------------------
#define ASTG 18432             // 2 planes x 64 rows x 144B

__global__ __launch_bounds__(128, 3) void attn_mma(const uint32_t* __restrict__ qf,
                                                   const uint32_t* __restrict__ kf_,
                                                   const uint32_t* __restrict__ vf_,
                                                   const int* __restrict__ mask,
                                                   float* __restrict__ pO,
                                                   float* __restrict__ pml)
{
    extern __shared__ uint32_t dynsm[];
    const uint32_t sb = smem_u32(dynsm);
    float* sMkF = (float*)(dynsm + 2 * (ASTG / 4));   // 64 float addends
    uint32_t* sQ = dynsm;          // phase 1 only: 64 rows x 36 words

    const int tid = threadIdx.x;
    const int warp = tid >> 5;
    const int lane = tid & 31;
    const int r4 = lane >> 2, q4 = lane & 3;
    const int qt = blockIdx.x;     // 0..31
    const int bh = blockIdx.y;     // 0..31
    const int sp = blockIdx.z;     // 0..1
    const int b = bh >> 4;
    const int ktBase = sp * TILES_PER_SPLIT;
    const size_t headW = (size_t)bh * NS * (HDIM / 2);

    // ---- Phase 1: stage Q (fp16 plane), load persistent A-frags ----
    {
        const uint32_t* pQ = qf + headW + (size_t)qt * 64 * 32;
#pragma unroll
        for (int it = 0; it < 4; it++) {
            int gi = tid + it * 128;       // 0..511
            int row = gi >> 3, w4 = (gi & 7) * 4;
            *(uint4*)(sQ + row * 36 + w4) = *(const uint4*)(pQ + row * 32 + w4);
        }
    }
    __syncthreads();
    uint32_t Qf[4][4];
#pragma unroll
    for (int kf = 0; kf < 4; kf++) {
        int off = (16 * warp + r4) * 36 + 8 * kf + q4;
        Qf[kf][0] = sQ[off];          Qf[kf][1] = sQ[off + 8 * 36];
        Qf[kf][2] = sQ[off + 4];      Qf[kf][3] = sQ[off + 8 * 36 + 4];
    }
    __syncthreads();   // stage area reusable

    const uint32_t* srcK = kf_ + headW;
    const uint32_t* srcV = vf_ + headW;
    auto issue = [&](int stage, int kt) {
#pragma unroll
        for (int it = 0; it < 8; it++) {
            int gi = tid + it * 128;       // 0..1023
            int pl = gi >> 9, gg = gi & 511;
            int row = gg >> 3, seg = gg & 7;
            const uint32_t* src = (pl ? srcV : srcK) + (size_t)kt * 2048 + row * 32 + seg * 4;
            uint32_t dst = sb + stage * ASTG + pl * 9216 + row * 144 + seg * 16;
            cp16(dst, src);
        }
        cp_commit();
    };

    // K frag base: rows (lane&7) within nf block, unit = lane>>3 (4 units = k0..31)
    const uint32_t kBase = (uint32_t)((lane & 7) * 144 + (lane >> 3) * 16);
    // V frag base (trans): rows (lane&15), col block pair selector lane>>4
    const uint32_t vBase = (uint32_t)(9216 + (lane & 15) * 144 + (lane >> 4) * 16);

    float O[8][4];
    float mI0 = -INFINITY, mI1 = -INFINITY, lI0 = 0.f, lI1 = 0.f;
#pragma unroll
    for (int nf = 0; nf < 8; nf++)
#pragma unroll
        for (int c = 0; c < 4; c++) O[nf][c] = 0.f;

    const int* mrow = mask + (size_t)b * NS;
    float mkldF = (tid < 64 && mrow[ktBase * 64 + tid]) ? -9e9f : 0.f;

    issue(0, ktBase);
    issue(1, ktBase + 1);

    for (int t = 0; t < TILES_PER_SPLIT; t++) {
        const int kt = ktBase + t;
        if (tid < 64) sMkF[tid] = mkldF;
        if (t < TILES_PER_SPLIT - 1) cp_wait<1>(); else cp_wait<0>();
        __syncthreads();
        const uint32_t sStage = sb + (t & 1) * ASTG;

        // ---- S = mask_addend + Q K^T (fp16 single) ----
        float S[8][4];
#pragma unroll
        for (int nf = 0; nf < 8; nf++) {
            float2 ma = *(const float2*)(sMkF + 8 * nf + 2 * q4);
            S[nf][0] = ma.x; S[nf][1] = ma.y;
            S[nf][2] = ma.x; S[nf][3] = ma.y;
        }
#pragma unroll
        for (int nf = 0; nf < 8; nf++) {
            uint32_t kb[4], kb2[4];
            ldsm_x4(kb[0], kb[1], kb[2], kb[3], sStage + kBase + (uint32_t)(nf * 1152));
            ldsm_x4(kb2[0], kb2[1], kb2[2], kb2[3],
                    sStage + kBase + (uint32_t)(nf * 1152 + 64));
            MMAH16816(S[nf], Qf[0], kb);
            MMAH16816(S[nf], Qf[1], kb + 2);
            MMAH16816(S[nf], Qf[2], kb2);
            MMAH16816(S[nf], Qf[3], kb2 + 2);
        }

        // ---- online softmax (exp2 domain) ----
        float mt0 = -INFINITY, mt1 = -INFINITY;
#pragma unroll
        for (int nf = 0; nf < 8; nf++) {
            mt0 = fmaxf(mt0, fmaxf(S[nf][0], S[nf][1]));
            mt1 = fmaxf(mt1, fmaxf(S[nf][2], S[nf][3]));
        }
        mt0 = fmaxf(mt0, __shfl_xor_sync(0xffffffffu, mt0, 1));
        mt0 = fmaxf(mt0, __shfl_xor_sync(0xffffffffu, mt0, 2));
        mt1 = fmaxf(mt1, __shfl_xor_sync(0xffffffffu, mt1, 1));
        mt1 = fmaxf(mt1, __shfl_xor_sync(0xffffffffu, mt1, 2));

        float mN0 = fmaxf(mI0, mt0), mN1 = fmaxf(mI1, mt1);
        float f0 = ex2f(mI0 - mN0), f1 = ex2f(mI1 - mN1);
        float rs0 = 0.f, rs1 = 0.f;
#pragma unroll
        for (int nf = 0; nf < 8; nf++) {
            S[nf][0] = ex2f(S[nf][0] - mN0);
            S[nf][1] = ex2f(S[nf][1] - mN0);
            S[nf][2] = ex2f(S[nf][2] - mN1);
            S[nf][3] = ex2f(S[nf][3] - mN1);
            rs0 += S[nf][0] + S[nf][1];
            rs1 += S[nf][2] + S[nf][3];
        }
        rs0 += __shfl_xor_sync(0xffffffffu, rs0, 1);
        rs0 += __shfl_xor_sync(0xffffffffu, rs0, 2);
        rs1 += __shfl_xor_sync(0xffffffffu, rs1, 1);
        rs1 += __shfl_xor_sync(0xffffffffu, rs1, 2);
        lI0 = lI0 * f0 + rs0;
        lI1 = lI1 * f1 + rs1;
        mI0 = mN0; mI1 = mN1;
#pragma unroll
        for (int nf = 0; nf < 8; nf++) {
            O[nf][0] *= f0; O[nf][1] *= f0;
            O[nf][2] *= f1; O[nf][3] *= f1;
        }

        // ---- pack P to fp16 A-frags ----
        uint32_t Pa[4][4];
#pragma unroll
        for (int kf = 0; kf < 4; kf++) {
            Pa[kf][0] = pack_h2(S[2*kf][0],     S[2*kf][1]);
            Pa[kf][1] = pack_h2(S[2*kf][2],     S[2*kf][3]);
            Pa[kf][2] = pack_h2(S[2*kf + 1][0], S[2*kf + 1][1]);
            Pa[kf][3] = pack_h2(S[2*kf + 1][2], S[2*kf + 1][3]);
        }

        // ---- O += P V (fp16 single; one x4.trans serves two nf) ----
#pragma unroll
        for (int kf = 0; kf < 4; kf++) {
            uint32_t abase = sStage + vBase + (uint32_t)(kf * 2304);
#pragma unroll
            for (int nfp = 0; nfp < 4; nfp++) {
                uint32_t vv[4];
                ldsm_x4_t(vv[0], vv[1], vv[2], vv[3], abase + nfp * 32);
                MMAH16816(O[2 * nfp],     Pa[kf], vv);
                MMAH16816(O[2 * nfp + 1], Pa[kf], vv + 2);
            }
        }

        __syncthreads();
        if (t + 2 < TILES_PER_SPLIT) issue(t & 1, kt + 2);
        if (t + 1 < TILES_PER_SPLIT && tid < 64)
            mkldF = mrow[(kt + 1) * 64 + tid] ? -9e9f : 0.f;
    }

    // ---- write UNNORMALIZED partials + (m,l) ----
    const int tile = bh * 32 + qt;
    float* po = pO + (size_t)sp * (1024 * 64 * 64) + (size_t)tile * (64 * 64);
    float* pm = pml + (size_t)sp * (1024 * 64 * 2) + (size_t)tile * (64 * 2);
    const int row0 = 16 * warp + r4;
#pragma unroll
    for (int nf = 0; nf < 8; nf++) {
        *(float2*)(po + row0 * 64 + 8 * nf + 2 * q4)       = make_float2(O[nf][0], O[nf][1]);
        *(float2*)(po + (row0 + 8) * 64 + 8 * nf + 2 * q4) = make_float2(O[nf][2], O[nf][3]);
    }
    if (q4 == 0) {
        *(float2*)(pm + row0 * 2)       = make_float2(mI0, lI0);
        *(float2*)(pm + (row0 + 8) * 2) = make_float2(mI1, lI1);
    }
}

// ---------------------------------------------------------------------------
// Combine split-KV partials -> ctx bf16 hi/lo planes [b][s][h*64+e]
// ---------------------------------------------------------------------------
__global__ __launch_bounds__(256) void attn_combine(const float* __restrict__ pO,
                                                    const float* __restrict__ pml,
                                                    uint32_t* __restrict__ ch_out,
                                                    uint32_t* __restrict__ cl_out)
{
    const int gid = blockIdx.x * 256 + threadIdx.x;   // 0..262143
    const int grp = gid & 3;
    const int rowg = gid >> 2;
    const int r = rowg & 63;
    const int tile = rowg >> 6;
    const int qt = tile & 31, bh = tile >> 5;
    const size_t SPO = (size_t)1024 * 64 * 64;
    const size_t SPM = (size_t)1024 * 64 * 2;
    const size_t obase = (size_t)rowg * 64 + grp * 16;
    const size_t mlbase = (size_t)rowg * 2;

    float2 ml0 = *(const float2*)(pml + mlbase);
    float2 ml1 = *(const float2*)(pml + SPM + mlbase);
    float m = fmaxf(ml0.x, ml1.x);
    float f0 = ex2f(ml0.x - m), f1 = ex2f(ml1.x - m);
    float inv = 1.f / (ml0.y * f0 + ml1.y * f1);
    f0 *= inv; f1 *= inv;

    uint32_t hw[8], lw[8];
#pragma unroll
    for (int c4 = 0; c4 < 4; c4++) {
        float4 a = *(const float4*)(pO + obase + c4 * 4);
        float4 bb = *(const float4*)(pO + SPO + obase + c4 * 4);
        float o0 = a.x * f0 + bb.x * f1;
        float o1 = a.y * f0 + bb.y * f1;
        float o2 = a.z * f0 + bb.z * f1;
        float o3 = a.w * f0 + bb.w * f1;
        cvt_pair(o0, o1, hw[c4 * 2], lw[c4 * 2]);
        cvt_pair(o2, o3, hw[c4 * 2 + 1], lw[c4 * 2 + 1]);
    }

    const int b = bh >> 4, h = bh & 15;
    const int srow = qt * 64 + r;
    const size_t wo = (((size_t)(b * NS + srow)) * ND + h * HDIM + grp * 16) >> 1;
    *(uint4*)(ch_out + wo)     = make_uint4(hw[0], hw[1], hw[2], hw[3]);
    *(uint4*)(ch_out + wo + 4) = make_uint4(hw[4], hw[5], hw[6], hw[7]);
    *(uint4*)(cl_out + wo)     = make_uint4(lw[0], lw[1], lw[2], lw[3]);
    *(uint4*)(cl_out + wo + 4) = make_uint4(lw[4], lw[5], lw[6], lw[7]);
}

extern "C" void kernel_launch(void* const* d_in, const int* in_sizes, int n_in,
                              void* d_out, int out_size)
{
    const float* q  = (const float*)d_in[0];
    const float* k  = (const float*)d_in[1];
    const float* v  = (const float*)d_in[2];
    const int* mask = (const int*)d_in[3];
    const float* Wq = (const float*)d_in[4];
    const float* bq = (const float*)d_in[5];
    const float* Wk = (const float*)d_in[6];
    const float* bk = (const float*)d_in[7];
    const float* Wv = (const float*)d_in[8];
    const float* bv = (const float*)d_in[9];
    const float* Wo = (const float*)d_in[10];
    const float* bo = (const float*)d_in[11];
    float* out = (float*)d_out;

    uint32_t *inqh, *inql, *inkh, *inkl, *invh, *invl, *wh, *wl;
    uint32_t *qf_d, *kf_d, *vf_d, *ch_d, *cl_d;
    float *pO_d, *pml_d;
    cudaGetSymbolAddress((void**)&inqh, g_inqh); cudaGetSymbolAddress((void**)&inql, g_inql);
    cudaGetSymbolAddress((void**)&inkh, g_inkh); cudaGetSymbolAddress((void**)&inkl, g_inkl);
    cudaGetSymbolAddress((void**)&invh, g_invh); cudaGetSymbolAddress((void**)&invl, g_invl);
    cudaGetSymbolAddress((void**)&wh, g_wh);     cudaGetSymbolAddress((void**)&wl, g_wl);
    cudaGetSymbolAddress((void**)&qf_d, g_qf);
    cudaGetSymbolAddress((void**)&kf_d, g_kf);
    cudaGetSymbolAddress((void**)&vf_d, g_vf);
    cudaGetSymbolAddress((void**)&ch_d, g_ch);   cudaGetSymbolAddress((void**)&cl_d, g_cl);
    cudaGetSymbolAddress((void**)&pO_d, g_pO);   cudaGetSymbolAddress((void**)&pml_d, g_pml);

    const int WSTRIDE = ND * RWORDS;
    const int NIN = MROWS * ND / 8;
    const int NW  = ND * ND / 8;

    CvtArgs ca;
    ca.s[0] = q;  ca.ph[0] = inqh; ca.pl[0] = inql; ca.cnt[0] = NIN;
    ca.s[1] = k;  ca.ph[1] = inkh; ca.pl[1] = inkl; ca.cnt[1] = NIN;
    ca.s[2] = v;  ca.ph[2] = invh; ca.pl[2] = invl; ca.cnt[2] = NIN;
    ca.s[3] = Wq; ca.ph[3] = wh;                ca.pl[3] = wl;                ca.cnt[3] = NW;
    ca.s[4] = Wk; ca.ph[4] = wh + WSTRIDE;      ca.pl[4] = wl + WSTRIDE;      ca.cnt[4] = NW;
    ca.s[5] = Wv; ca.ph[5] = wh + 2 * WSTRIDE;  ca.pl[5] = wl + 2 * WSTRIDE;  ca.cnt[5] = NW;
    ca.s[6] = Wo; ca.ph[6] = wh + 3 * WSTRIDE;  ca.pl[6] = wl + 3 * WSTRIDE;  ca.cnt[6] = NW;
    cvt_planes7<<<dim3((NIN + 255) / 256, 1, 7), 256>>>(ca);

    const int smem_gemm = 2 * GSTAGE_B;                 // 81920
    cudaFuncSetAttribute(gemm_planes, cudaFuncAttributeMaxDynamicSharedMemorySize, smem_gemm);
    const int smem_attn = 2 * ASTG + 64 * 4;            // 37120
    cudaFuncSetAttribute(attn_mma, cudaFuncAttributeMaxDynamicSharedMemorySize, smem_attn);

    // QKV projections -> fp16 head planes (Q pre-scaled)
    GP aq{inqh, inql, wh, wl, bq, nullptr, qf_d, QSCALE};
    GP ak{inkh, inkl, wh + WSTRIDE, wl + WSTRIDE, bk, nullptr, kf_d, 1.f};
    GP av{invh, invl, wh + 2 * WSTRIDE, wl + 2 * WSTRIDE, bv, nullptr, vf_d, 1.f};
    gemm_planes<<<dim3(ND / 128, MROWS / 128, 3), 256, smem_gemm>>>(aq, ak, av, 1);

    // attention split-KV x2 (fp16) -> partials
    attn_mma<<<dim3(NS / 64, NB * NH, NSPLIT), 128, smem_attn>>>(
        qf_d, kf_d, vf_d, mask, pO_d, pml_d);

    // combine partials -> ctx bf16 planes
    attn_combine<<<1024, 256>>>(pO_d, pml_d, ch_d, cl_d);

    // output projection (split-3 bf16, fp32 out)
    GP ao{ch_d, cl_d, wh + 3 * WSTRIDE, wl + 3 * WSTRIDE, bo, out, nullptr, 1.f};
    gemm_planes<<<dim3(ND / 128, MROWS / 128, 1), 256, smem_gemm>>>(ao, ao, ao, 0);
}

// round 14
// speedup vs baseline: 2.2863x; 1.5838x over previous
#include <cuda_runtime.h>
#include <cuda_bf16.h>
#include <cuda_fp16.h>
#include <math.h>
#include <stdint.h>

#define NB 2
#define NS 2048
#define ND 1024
#define NH 16
#define HDIM 64
#define MROWS (NB*NS)
#define RWORDS (ND/2)          // 512 u32 words per 1024-elem fp16 row
#define NSPLIT 2
#define TILES_PER_SPLIT (NS / 64 / NSPLIT)   // 16

// ---- static scratch (no allocations allowed) ----
// fp16 single planes: inputs (row layout), weights, q/k/v (head layout), ctx
__device__ uint32_t g_inq[MROWS*RWORDS], g_ink[MROWS*RWORDS], g_inv[MROWS*RWORDS];
__device__ uint32_t g_w[4*ND*RWORDS];
__device__ uint32_t g_qf[NB*NH*NS*HDIM/2];
__device__ uint32_t g_kf[NB*NH*NS*HDIM/2];
__device__ uint32_t g_vf[NB*NH*NS*HDIM/2];
__device__ uint32_t g_cf[MROWS*RWORDS];
// split-KV partials
__device__ float g_pO[NSPLIT * 1024 * 64 * 64];
__device__ float g_pml[NSPLIT * 1024 * 64 * 2];

#define QSCALE 0.18033688011f      // 0.125 * log2(e)

#define MMAH16816(c, a, b) \
  asm volatile("mma.sync.aligned.m16n8k16.row.col.f32.f16.f16.f32 " \
    "{%0,%1,%2,%3}, {%4,%5,%6,%7}, {%8,%9}, {%0,%1,%2,%3};" \
    : "+f"((c)[0]), "+f"((c)[1]), "+f"((c)[2]), "+f"((c)[3]) \
    : "r"((a)[0]), "r"((a)[1]), "r"((a)[2]), "r"((a)[3]), \
      "r"((b)[0]), "r"((b)[1]))

__device__ __forceinline__ uint32_t pack_h2(float x, float y) {
    __half2 h = __floats2half2_rn(x, y);
    return *reinterpret_cast<uint32_t*>(&h);
}
__device__ __forceinline__ float ex2f(float x) {
    float y; asm("ex2.approx.ftz.f32 %0, %1;" : "=f"(y) : "f"(x)); return y;
}
__device__ __forceinline__ uint32_t smem_u32(const void* p) {
    uint32_t a;
    asm("{ .reg .u64 t; cvta.to.shared.u64 t, %1; cvt.u32.u64 %0, t; }" : "=r"(a) : "l"(p));
    return a;
}
__device__ __forceinline__ void ldsm_x4(uint32_t& r0, uint32_t& r1, uint32_t& r2, uint32_t& r3,
                                        uint32_t a) {
    asm volatile("ldmatrix.sync.aligned.m8n8.x4.shared.b16 {%0,%1,%2,%3}, [%4];"
                 : "=r"(r0), "=r"(r1), "=r"(r2), "=r"(r3) : "r"(a));
}
__device__ __forceinline__ void ldsm_x4_t(uint32_t& r0, uint32_t& r1, uint32_t& r2, uint32_t& r3,
                                          uint32_t a) {
    asm volatile("ldmatrix.sync.aligned.m8n8.x4.trans.shared.b16 {%0,%1,%2,%3}, [%4];"
                 : "=r"(r0), "=r"(r1), "=r"(r2), "=r"(r3) : "r"(a));
}
__device__ __forceinline__ void cp16(uint32_t dst, const void* src) {
    asm volatile("cp.async.cg.shared.global [%0], [%1], 16;" :: "r"(dst), "l"(src) : "memory");
}
__device__ __forceinline__ void cp_commit() {
    asm volatile("cp.async.commit_group;" ::: "memory");
}
template<int N> __device__ __forceinline__ void cp_wait() {
    asm volatile("cp.async.wait_group %0;" :: "n"(N) : "memory");
}

// ---------------------------------------------------------------------------
// fp32 -> fp16 single-plane converter, 7 tensors in one launch
// ---------------------------------------------------------------------------
struct CvtArgs {
    const float* s[7];
    uint32_t* pf[7];
    int cnt[7];          // uint4-out groups (8 floats) per slice
};

__global__ __launch_bounds__(256) void cvt_planes7(CvtArgs a)
{
    int z = blockIdx.z;
    int i = blockIdx.x * 256 + threadIdx.x;
    if (i >= a.cnt[z]) return;
    const float* s = a.s[z];
    float4 v0 = ((const float4*)s)[2 * i];
    float4 v1 = ((const float4*)s)[2 * i + 1];
    ((uint4*)a.pf[z])[i] = make_uint4(pack_h2(v0.x, v0.y), pack_h2(v0.z, v0.w),
                                      pack_h2(v1.x, v1.y), pack_h2(v1.z, v1.w));
}

// ---------------------------------------------------------------------------
// fp16 single-plane GEMM: C[m][n] = sum_k A[m,k]*W[n,k] (+bias)*scale
// cp.async 2-stage, 2 CTAs/SM. 1 MMA per fragment pair.
// stage (bytes): A[0..10239] B[10240..20479], row pitch 80B.
// headmode=1: write fp16 plane in head layout; headmode=0: fp32 row-major.
// ---------------------------------------------------------------------------
struct GP {
    const uint32_t *Af, *Bf;
    const float* bias;
    float* C; uint32_t *Pf; float scale;
};
#define GSTAGE_B 20480

__global__ __launch_bounds__(256, 2) void gemm_planes(GP a0, GP a1, GP a2, int headmode)
{
    GP g = (blockIdx.z == 0) ? a0 : (blockIdx.z == 1) ? a1 : a2;
    extern __shared__ uint32_t smg[];
    const uint32_t sb = smem_u32(smg);

    const int tid = threadIdx.x;
    const int warp = tid >> 5;
    const int lane = tid & 31;
    const int r4 = lane >> 2, q4 = lane & 3;
    const int m0w = (warp >> 2) * 64;
    const int n0w = (warp & 3) * 32;
    const int mBase = blockIdx.y * 128;
    const int nBase = blockIdx.x * 128;

    const uint32_t* srcA = g.Af + (size_t)mBase * RWORDS;
    const uint32_t* srcB = g.Bf + (size_t)nBase * RWORDS;

    // A frag: 16 rows x 32B; lanes 0-15 rows, lanes 16-31 +16B (k8-15 group)
    const uint32_t aOff = (uint32_t)((m0w + (lane & 15)) * 80 + (lane >> 4) * 16);
    // B frag pair: lanes {0-7,8-15} nf block rows k0-7/k8-15; lanes {16-31} +8 rows
    const uint32_t bOff = (uint32_t)(10240 +
        (n0w + ((lane >> 4) & 1) * 8 + (lane & 7)) * 80 + ((lane >> 3) & 1) * 16);

    float acc[4][4][4];
#pragma unroll
    for (int mf = 0; mf < 4; mf++)
#pragma unroll
        for (int nf = 0; nf < 4; nf++)
#pragma unroll
            for (int c = 0; c < 4; c++) acc[mf][nf][c] = 0.f;

    auto issue = [&](int stage, int ch) {
#pragma unroll
        for (int it = 0; it < 4; it++) {
            int gi = tid + it * 256;       // 0..1023
            int pl = gi >> 9, gg = gi & 511;
            int row = gg >> 2, seg = gg & 3;
            const uint32_t* src = (pl ? srcB : srcA) + (size_t)row * RWORDS + ch * 16 + seg * 4;
            uint32_t dst = sb + stage * GSTAGE_B + pl * 10240 + row * 80 + seg * 16;
            cp16(dst, src);
        }
        cp_commit();
    };

    issue(0, 0);
    issue(1, 1);

    for (int ch = 0; ch < 32; ch++) {
        if (ch < 31) cp_wait<1>(); else cp_wait<0>();
        __syncthreads();
        const uint32_t sBase = sb + (ch & 1) * GSTAGE_B;

#pragma unroll
        for (int ks = 0; ks < 2; ks++) {
            const uint32_t ko = ks * 32;
            uint32_t bfr[2][4];
#pragma unroll
            for (int nfp = 0; nfp < 2; nfp++)
                ldsm_x4(bfr[nfp][0], bfr[nfp][1], bfr[nfp][2], bfr[nfp][3],
                        sBase + bOff + nfp * 1280 + ko);
#pragma unroll
            for (int mf = 0; mf < 4; mf++) {
                uint32_t af[4];
                ldsm_x4(af[0], af[1], af[2], af[3], sBase + aOff + mf * 1280 + ko);
#pragma unroll
                for (int nfp = 0; nfp < 2; nfp++) {
                    MMAH16816(acc[mf][2 * nfp],     af, bfr[nfp]);
                    MMAH16816(acc[mf][2 * nfp + 1], af, bfr[nfp] + 2);
                }
            }
        }
        __syncthreads();
        if (ch + 2 < 32) issue(ch & 1, ch + 2);
    }

#pragma unroll
    for (int nf = 0; nf < 4; nf++) {
        const int n = nBase + n0w + nf * 8 + q4 * 2;
        const float b0 = __ldg(g.bias + n);
        const float b1 = __ldg(g.bias + n + 1);
#pragma unroll
        for (int mf = 0; mf < 4; mf++) {
#pragma unroll
            for (int half = 0; half < 2; half++) {
                const int m = mBase + m0w + mf * 16 + r4 + half * 8;
                float v0 = (acc[mf][nf][half * 2] + b0) * g.scale;
                float v1 = (acc[mf][nf][half * 2 + 1] + b1) * g.scale;
                if (headmode) {
                    int b = m >> 11, s = m & (NS - 1);
                    int hh = n >> 6, e = n & 63;
                    size_t wo = (((size_t)((b * NH + hh) * NS + s)) * HDIM + e) >> 1;
                    g.Pf[wo] = pack_h2(v0, v1);
                } else {
                    *(float2*)(g.C + (size_t)m * ND + n) = make_float2(v0, v1);
                }
            }
        }
    }
}

// ---------------------------------------------------------------------------
// fp16 tensor-core flash attention, split-KV x2 (unchanged from R13).
// BQ=64, 128 threads, 3 CTAs/SM. Additive mask, exp2 softmax, partials out.
// stage (bytes): Kf[0..9215] Vf[9216..18431]; 2 stages; maskF after.
// ---------------------------------------------------------------------------
#define ASTG 18432

__global__ __launch_bounds__(128, 3) void attn_mma(const uint32_t* __restrict__ qf,
                                                   const uint32_t* __restrict__ kf_,
                                                   const uint32_t* __restrict__ vf_,
                                                   const int* __restrict__ mask,
                                                   float* __restrict__ pO,
                                                   float* __restrict__ pml)
{
    extern __shared__ uint32_t dynsm[];
    const uint32_t sb = smem_u32(dynsm);
    float* sMkF = (float*)(dynsm + 2 * (ASTG / 4));
    uint32_t* sQ = dynsm;          // phase 1 only: 64 rows x 36 words

    const int tid = threadIdx.x;
    const int warp = tid >> 5;
    const int lane = tid & 31;
    const int r4 = lane >> 2, q4 = lane & 3;
    const int qt = blockIdx.x;
    const int bh = blockIdx.y;
    const int sp = blockIdx.z;
    const int b = bh >> 4;
    const int ktBase = sp * TILES_PER_SPLIT;
    const size_t headW = (size_t)bh * NS * (HDIM / 2);

    {
        const uint32_t* pQ = qf + headW + (size_t)qt * 64 * 32;
#pragma unroll
        for (int it = 0; it < 4; it++) {
            int gi = tid + it * 128;
            int row = gi >> 3, w4 = (gi & 7) * 4;
            *(uint4*)(sQ + row * 36 + w4) = *(const uint4*)(pQ + row * 32 + w4);
        }
    }
    __syncthreads();
    uint32_t Qf[4][4];
#pragma unroll
    for (int kf = 0; kf < 4; kf++) {
        int off = (16 * warp + r4) * 36 + 8 * kf + q4;
        Qf[kf][0] = sQ[off];          Qf[kf][1] = sQ[off + 8 * 36];
        Qf[kf][2] = sQ[off + 4];      Qf[kf][3] = sQ[off + 8 * 36 + 4];
    }
    __syncthreads();

    const uint32_t* srcK = kf_ + headW;
    const uint32_t* srcV = vf_ + headW;
    auto issue = [&](int stage, int kt) {
#pragma unroll
        for (int it = 0; it < 8; it++) {
            int gi = tid + it * 128;
            int pl = gi >> 9, gg = gi & 511;
            int row = gg >> 3, seg = gg & 7;
            const uint32_t* src = (pl ? srcV : srcK) + (size_t)kt * 2048 + row * 32 + seg * 4;
            uint32_t dst = sb + stage * ASTG + pl * 9216 + row * 144 + seg * 16;
            cp16(dst, src);
        }
        cp_commit();
    };

    const uint32_t kBase = (uint32_t)((lane & 7) * 144 + (lane >> 3) * 16);
    const uint32_t vBase = (uint32_t)(9216 + (lane & 15) * 144 + (lane >> 4) * 16);

    float O[8][4];
    float mI0 = -INFINITY, mI1 = -INFINITY, lI0 = 0.f, lI1 = 0.f;
#pragma unroll
    for (int nf = 0; nf < 8; nf++)
#pragma unroll
        for (int c = 0; c < 4; c++) O[nf][c] = 0.f;

    const int* mrow = mask + (size_t)b * NS;
    float mkldF = (tid < 64 && mrow[ktBase * 64 + tid]) ? -9e9f : 0.f;

    issue(0, ktBase);
    issue(1, ktBase + 1);

    for (int t = 0; t < TILES_PER_SPLIT; t++) {
        const int kt = ktBase + t;
        if (tid < 64) sMkF[tid] = mkldF;
        if (t < TILES_PER_SPLIT - 1) cp_wait<1>(); else cp_wait<0>();
        __syncthreads();
        const uint32_t sStage = sb + (t & 1) * ASTG;

        float S[8][4];
#pragma unroll
        for (int nf = 0; nf < 8; nf++) {
            float2 ma = *(const float2*)(sMkF + 8 * nf + 2 * q4);
            S[nf][0] = ma.x; S[nf][1] = ma.y;
            S[nf][2] = ma.x; S[nf][3] = ma.y;
        }
#pragma unroll
        for (int nf = 0; nf < 8; nf++) {
            uint32_t kb[4], kb2[4];
            ldsm_x4(kb[0], kb[1], kb[2], kb[3], sStage + kBase + (uint32_t)(nf * 1152));
            ldsm_x4(kb2[0], kb2[1], kb2[2], kb2[3],
                    sStage + kBase + (uint32_t)(nf * 1152 + 64));
            MMAH16816(S[nf], Qf[0], kb);
            MMAH16816(S[nf], Qf[1], kb + 2);
            MMAH16816(S[nf], Qf[2], kb2);
            MMAH16816(S[nf], Qf[3], kb2 + 2);
        }

        float mt0 = -INFINITY, mt1 = -INFINITY;
#pragma unroll
        for (int nf = 0; nf < 8; nf++) {
            mt0 = fmaxf(mt0, fmaxf(S[nf][0], S[nf][1]));
            mt1 = fmaxf(mt1, fmaxf(S[nf][2], S[nf][3]));
        }
        mt0 = fmaxf(mt0, __shfl_xor_sync(0xffffffffu, mt0, 1));
        mt0 = fmaxf(mt0, __shfl_xor_sync(0xffffffffu, mt0, 2));
        mt1 = fmaxf(mt1, __shfl_xor_sync(0xffffffffu, mt1, 1));
        mt1 = fmaxf(mt1, __shfl_xor_sync(0xffffffffu, mt1, 2));

        float mN0 = fmaxf(mI0, mt0), mN1 = fmaxf(mI1, mt1);
        float f0 = ex2f(mI0 - mN0), f1 = ex2f(mI1 - mN1);
        float rs0 = 0.f, rs1 = 0.f;
#pragma unroll
        for (int nf = 0; nf < 8; nf++) {
            S[nf][0] = ex2f(S[nf][0] - mN0);
            S[nf][1] = ex2f(S[nf][1] - mN0);
            S[nf][2] = ex2f(S[nf][2] - mN1);
            S[nf][3] = ex2f(S[nf][3] - mN1);
            rs0 += S[nf][0] + S[nf][1];
            rs1 += S[nf][2] + S[nf][3];
        }
        rs0 += __shfl_xor_sync(0xffffffffu, rs0, 1);
        rs0 += __shfl_xor_sync(0xffffffffu, rs0, 2);
        rs1 += __shfl_xor_sync(0xffffffffu, rs1, 1);
        rs1 += __shfl_xor_sync(0xffffffffu, rs1, 2);
        lI0 = lI0 * f0 + rs0;
        lI1 = lI1 * f1 + rs1;
        mI0 = mN0; mI1 = mN1;
#pragma unroll
        for (int nf = 0; nf < 8; nf++) {
            O[nf][0] *= f0; O[nf][1] *= f0;
            O[nf][2] *= f1; O[nf][3] *= f1;
        }

        uint32_t Pa[4][4];
#pragma unroll
        for (int kf = 0; kf < 4; kf++) {
            Pa[kf][0] = pack_h2(S[2*kf][0],     S[2*kf][1]);
            Pa[kf][1] = pack_h2(S[2*kf][2],     S[2*kf][3]);
            Pa[kf][2] = pack_h2(S[2*kf + 1][0], S[2*kf + 1][1]);
            Pa[kf][3] = pack_h2(S[2*kf + 1][2], S[2*kf + 1][3]);
        }

#pragma unroll
        for (int kf = 0; kf < 4; kf++) {
            uint32_t abase = sStage + vBase + (uint32_t)(kf * 2304);
#pragma unroll
            for (int nfp = 0; nfp < 4; nfp++) {
                uint32_t vv[4];
                ldsm_x4_t(vv[0], vv[1], vv[2], vv[3], abase + nfp * 32);
                MMAH16816(O[2 * nfp],     Pa[kf], vv);
                MMAH16816(O[2 * nfp + 1], Pa[kf], vv + 2);
            }
        }

        __syncthreads();
        if (t + 2 < TILES_PER_SPLIT) issue(t & 1, kt + 2);
        if (t + 1 < TILES_PER_SPLIT && tid < 64)
            mkldF = mrow[(kt + 1) * 64 + tid] ? -9e9f : 0.f;
    }

    const int tile = bh * 32 + qt;
    float* po = pO + (size_t)sp * (1024 * 64 * 64) + (size_t)tile * (64 * 64);
    float* pm = pml + (size_t)sp * (1024 * 64 * 2) + (size_t)tile * (64 * 2);
    const int row0 = 16 * warp + r4;
#pragma unroll
    for (int nf = 0; nf < 8; nf++) {
        *(float2*)(po + row0 * 64 + 8 * nf + 2 * q4)       = make_float2(O[nf][0], O[nf][1]);
        *(float2*)(po + (row0 + 8) * 64 + 8 * nf + 2 * q4) = make_float2(O[nf][2], O[nf][3]);
    }
    if (q4 == 0) {
        *(float2*)(pm + row0 * 2)       = make_float2(mI0, lI0);
        *(float2*)(pm + (row0 + 8) * 2) = make_float2(mI1, lI1);
    }
}

// ---------------------------------------------------------------------------
// Combine split-KV partials -> ctx fp16 plane [b][s][h*64+e]
// ---------------------------------------------------------------------------
__global__ __launch_bounds__(256) void attn_combine(const float* __restrict__ pO,
                                                    const float* __restrict__ pml,
                                                    uint32_t* __restrict__ cf_out)
{
    const int gid = blockIdx.x * 256 + threadIdx.x;   // 0..262143
    const int grp = gid & 3;
    const int rowg = gid >> 2;
    const int r = rowg & 63;
    const int tile = rowg >> 6;
    const int qt = tile & 31, bh = tile >> 5;
    const size_t SPO = (size_t)1024 * 64 * 64;
    const size_t SPM = (size_t)1024 * 64 * 2;
    const size_t obase = (size_t)rowg * 64 + grp * 16;
    const size_t mlbase = (size_t)rowg * 2;

    float2 ml0 = *(const float2*)(pml + mlbase);
    float2 ml1 = *(const float2*)(pml + SPM + mlbase);
    float m = fmaxf(ml0.x, ml1.x);
    float f0 = ex2f(ml0.x - m), f1 = ex2f(ml1.x - m);
    float inv = 1.f / (ml0.y * f0 + ml1.y * f1);
    f0 *= inv; f1 *= inv;

    uint32_t w[8];
#pragma unroll
    for (int c4 = 0; c4 < 4; c4++) {
        float4 a = *(const float4*)(pO + obase + c4 * 4);
        float4 bb = *(const float4*)(pO + SPO + obase + c4 * 4);
        w[c4 * 2]     = pack_h2(a.x * f0 + bb.x * f1, a.y * f0 + bb.y * f1);
        w[c4 * 2 + 1] = pack_h2(a.z * f0 + bb.z * f1, a.w * f0 + bb.w * f1);
    }

    const int b = bh >> 4, h = bh & 15;
    const int srow = qt * 64 + r;
    const size_t wo = (((size_t)(b * NS + srow)) * ND + h * HDIM + grp * 16) >> 1;
    *(uint4*)(cf_out + wo)     = make_uint4(w[0], w[1], w[2], w[3]);
    *(uint4*)(cf_out + wo + 4) = make_uint4(w[4], w[5], w[6], w[7]);
}

extern "C" void kernel_launch(void* const* d_in, const int* in_sizes, int n_in,
                              void* d_out, int out_size)
{
    const float* q  = (const float*)d_in[0];
    const float* k  = (const float*)d_in[1];
    const float* v  = (const float*)d_in[2];
    const int* mask = (const int*)d_in[3];
    const float* Wq = (const float*)d_in[4];
    const float* bq = (const float*)d_in[5];
    const float* Wk = (const float*)d_in[6];
    const float* bk = (const float*)d_in[7];
    const float* Wv = (const float*)d_in[8];
    const float* bv = (const float*)d_in[9];
    const float* Wo = (const float*)d_in[10];
    const float* bo = (const float*)d_in[11];
    float* out = (float*)d_out;

    uint32_t *inq_d, *ink_d, *inv_d, *w_d;
    uint32_t *qf_d, *kf_d, *vf_d, *cf_d;
    float *pO_d, *pml_d;
    cudaGetSymbolAddress((void**)&inq_d, g_inq);
    cudaGetSymbolAddress((void**)&ink_d, g_ink);
    cudaGetSymbolAddress((void**)&inv_d, g_inv);
    cudaGetSymbolAddress((void**)&w_d, g_w);
    cudaGetSymbolAddress((void**)&qf_d, g_qf);
    cudaGetSymbolAddress((void**)&kf_d, g_kf);
    cudaGetSymbolAddress((void**)&vf_d, g_vf);
    cudaGetSymbolAddress((void**)&cf_d, g_cf);
    cudaGetSymbolAddress((void**)&pO_d, g_pO);
    cudaGetSymbolAddress((void**)&pml_d, g_pml);

    const int WSTRIDE = ND * RWORDS;
    const int NIN = MROWS * ND / 8;
    const int NW  = ND * ND / 8;

    CvtArgs ca;
    ca.s[0] = q;  ca.pf[0] = inq_d;            ca.cnt[0] = NIN;
    ca.s[1] = k;  ca.pf[1] = ink_d;            ca.cnt[1] = NIN;
    ca.s[2] = v;  ca.pf[2] = inv_d;            ca.cnt[2] = NIN;
    ca.s[3] = Wq; ca.pf[3] = w_d;              ca.cnt[3] = NW;
    ca.s[4] = Wk; ca.pf[4] = w_d + WSTRIDE;    ca.cnt[4] = NW;
    ca.s[5] = Wv; ca.pf[5] = w_d + 2*WSTRIDE;  ca.cnt[5] = NW;
    ca.s[6] = Wo; ca.pf[6] = w_d + 3*WSTRIDE;  ca.cnt[6] = NW;
    cvt_planes7<<<dim3((NIN + 255) / 256, 1, 7), 256>>>(ca);

    const int smem_gemm = 2 * GSTAGE_B;                 // 40960
    cudaFuncSetAttribute(gemm_planes, cudaFuncAttributeMaxDynamicSharedMemorySize, smem_gemm);
    const int smem_attn = 2 * ASTG + 64 * 4;            // 37120
    cudaFuncSetAttribute(attn_mma, cudaFuncAttributeMaxDynamicSharedMemorySize, smem_attn);

    // QKV projections -> fp16 head planes (Q pre-scaled)
    GP aq{inq_d, w_d, bq, nullptr, qf_d, QSCALE};
    GP ak{ink_d, w_d + WSTRIDE, bk, nullptr, kf_d, 1.f};
    GP av{inv_d, w_d + 2 * WSTRIDE, bv, nullptr, vf_d, 1.f};
    gemm_planes<<<dim3(ND / 128, MROWS / 128, 3), 256, smem_gemm>>>(aq, ak, av, 1);

    // attention split-KV x2 (fp16) -> partials
    attn_mma<<<dim3(NS / 64, NB * NH, NSPLIT), 128, smem_attn>>>(
        qf_d, kf_d, vf_d, mask, pO_d, pml_d);

    // combine partials -> ctx fp16 plane
    attn_combine<<<1024, 256>>>(pO_d, pml_d, cf_d);

    // output projection (fp16, fp32 out)
    GP ao{cf_d, w_d + 3 * WSTRIDE, bo, out, nullptr, 1.f};
    gemm_planes<<<dim3(ND / 128, MROWS / 128, 1), 256, smem_gemm>>>(ao, ao, ao, 0);
}